// round 9
// baseline (speedup 1.0000x reference)
#include <cuda_runtime.h>
#include <math.h>

#define Bq 256
#define Nn 512
#define NP1 513
#define Ss 32
#define Tt 33
#define DENT 256
#define DKEY 32
#define DIN 1024
#define DFUNC 256
#define DTYPE 259
#define HH 32
#define G4 128

// ---------------- scratch (static device globals; no allocations) ----------
__device__ float g_padkey[Bq * NP1 * DKEY];   // [b][n][k]
__device__ float g_func[Bq * DFUNC];
__device__ float g_A0[Bq * DFUNC];            // emb0@Wfc1^T + b_fc1 + func_embed
__device__ float g_M[DFUNC * DKEY];           // W_fc1 @ W_embed
__device__ float g_v[DFUNC];                  // W_fc1 @ b_embed
__device__ float g_mask0[Bq * NP1];
__device__ int   g_fs[Bq * NP1];              // first step n was selected (INT_MAX if never)
__device__ float g_Kacc[Bq * Tt * DKEY];      // inv_n * prefix sum of selected keys
__device__ float g_G[Bq * Tt * G4];           // x@Wih^T + b_ih + b_hh (precomputed gate input)
__device__ float g_H[Bq * Tt * HH];           // h after LSTM update at step t

// ---------------- pad_key = entity @ W_key^T + b_key -----------------------
// tile: 64 entity rows x 32 outputs, K=256 in chunks of 32
__global__ __launch_bounds__(256) void k_padkey(const float* __restrict__ ent,
                                                const float* __restrict__ Wk,
                                                const float* __restrict__ bk) {
    __shared__ float Wt[DENT * DKEY];   // [k][c]
    __shared__ float es[32 * 65];       // [kk][e], padded stride 65
    const int tid = threadIdx.x;
    const int r0 = blockIdx.x * 64;
    for (int idx = tid; idx < DENT * DKEY; idx += 256) {
        int c = idx >> 8, k = idx & 255;
        Wt[k * DKEY + c] = Wk[idx];
    }
    __syncthreads();
    const int e = tid & 63;
    const int c = (tid >> 6) * 8;
    float acc[8];
#pragma unroll
    for (int j = 0; j < 8; j++) acc[j] = 0.f;
    for (int kc = 0; kc < DENT; kc += 32) {
        for (int idx = tid; idx < 64 * 32; idx += 256) {
            int ee = idx >> 5, kk = idx & 31;
            es[kk * 65 + ee] = ent[(size_t)(r0 + ee) * DENT + kc + kk];
        }
        __syncthreads();
#pragma unroll
        for (int kk = 0; kk < 32; kk++) {
            float a = es[kk * 65 + e];
            const float4* w4 = (const float4*)&Wt[(kc + kk) * DKEY + c];
            float4 w0 = w4[0], w1 = w4[1];
            acc[0] += a * w0.x; acc[1] += a * w0.y;
            acc[2] += a * w0.z; acc[3] += a * w0.w;
            acc[4] += a * w1.x; acc[5] += a * w1.y;
            acc[6] += a * w1.z; acc[7] += a * w1.w;
        }
        __syncthreads();
    }
    int r = r0 + e;
    int b = r >> 9;                 // n = r - 512*b
    size_t off = (size_t)32 * (r + b) + c;   // = b*513*32 + n*32 + c
#pragma unroll
    for (int j = 0; j < 8; j++) g_padkey[off + j] = acc[j] + bk[c + j];
}

__global__ void k_endrow(const float* __restrict__ endemb) {
    g_padkey[((size_t)blockIdx.x * NP1 + Nn) * DKEY + threadIdx.x] = endemb[threadIdx.x];
}

// ---------------- func_embed = relu(type_mask @ W_func^T + b_func) ---------
__global__ __launch_bounds__(256) void k_funcembed(const float* __restrict__ tmask,
                                                   const float* __restrict__ Wf,
                                                   const float* __restrict__ bf) {
    __shared__ float ts[DTYPE];
    int b = blockIdx.x, j = threadIdx.x;
    for (int i = j; i < DTYPE; i += 256) ts[i] = tmask[b * DTYPE + i];
    __syncthreads();
    float a = bf[j];
    const float* wr = Wf + (size_t)j * DTYPE;
#pragma unroll 4
    for (int k = 0; k < DTYPE; k++) a += ts[k] * wr[k];
    g_func[b * DFUNC + j] = fmaxf(a, 0.f);
}

// ---------------- A0 = emb0 @ W_fc1^T + b_fc1 + func_embed (4 b / block) ---
__global__ __launch_bounds__(256) void k_A0(const float* __restrict__ emb,
                                            const float* __restrict__ W1,
                                            const float* __restrict__ b1) {
    __shared__ float es[4 * DIN];
    int b0 = blockIdx.x * 4;
    int j = threadIdx.x;
    for (int i = j; i < 4 * DIN; i += 256) es[i] = emb[(size_t)b0 * DIN + i];
    __syncthreads();
    float a0 = 0.f, a1 = 0.f, a2 = 0.f, a3 = 0.f;
    const float4* w4 = (const float4*)(W1 + (size_t)j * DIN);
    const float4* e4 = (const float4*)es;
#pragma unroll 4
    for (int k = 0; k < DIN / 4; k++) {
        float4 w = w4[k];
        float4 x0 = e4[k], x1 = e4[256 + k], x2 = e4[512 + k], x3 = e4[768 + k];
        a0 += w.x * x0.x + w.y * x0.y + w.z * x0.z + w.w * x0.w;
        a1 += w.x * x1.x + w.y * x1.y + w.z * x1.z + w.w * x1.w;
        a2 += w.x * x2.x + w.y * x2.y + w.z * x2.z + w.w * x2.w;
        a3 += w.x * x3.x + w.y * x3.y + w.z * x3.z + w.w * x3.w;
    }
    float bias = b1[j];
    g_A0[(b0 + 0) * DFUNC + j] = a0 + bias + g_func[(b0 + 0) * DFUNC + j];
    g_A0[(b0 + 1) * DFUNC + j] = a1 + bias + g_func[(b0 + 1) * DFUNC + j];
    g_A0[(b0 + 2) * DFUNC + j] = a2 + bias + g_func[(b0 + 2) * DFUNC + j];
    g_A0[(b0 + 3) * DFUNC + j] = a3 + bias + g_func[(b0 + 3) * DFUNC + j];
}

// ---------------- M = W_fc1 @ W_embed ; v = W_fc1 @ b_embed ----------------
__global__ __launch_bounds__(64) void k_Mv(const float* __restrict__ W1,
                                           const float* __restrict__ We,
                                           const float* __restrict__ be) {
    __shared__ float wr[DIN];
    int j = blockIdx.x, t = threadIdx.x;
    for (int i = t; i < DIN; i += 64) wr[i] = W1[(size_t)j * DIN + i];
    __syncthreads();
    if (t < DKEY) {
        float a = 0.f;
        for (int k = 0; k < DIN; k++) a += wr[k] * We[k * DKEY + t];
        g_M[j * DKEY + t] = a;
    } else if (t == DKEY) {
        float a = 0.f;
        for (int k = 0; k < DIN; k++) a += wr[k] * be[k];
        g_v[j] = a;
    }
}

// ---------------- mask0 + first-selection-step per (b,n) -------------------
__global__ __launch_bounds__(256) void k_maskprep(const float* __restrict__ avail,
                                                  const int* __restrict__ sel) {
    __shared__ int ss[Ss];
    int b = blockIdx.x, tid = threadIdx.x;
    if (tid < Ss) ss[tid] = sel[b * Ss + tid];
    __syncthreads();
    for (int n = tid; n < NP1; n += 256) {
        int fs = 0x7FFFFFFF;
#pragma unroll
        for (int s = 0; s < Ss; s++)
            if (ss[s] == n && s < fs) fs = s;
        float m = (n == Nn) ? 1.f : avail[b * Nn + n];
        if (fs < Ss) m = 1.f;   // teacher forcing: selected positions forced available
        g_mask0[b * NP1 + n] = m;
        g_fs[b * NP1 + n] = fs;
    }
}

// ---------------- Kacc: prefix sums of selected keys -----------------------
__global__ __launch_bounds__(32) void k_gather(const int* __restrict__ sel) {
    __shared__ int ss[Ss];
    int b = blockIdx.x, d = threadIdx.x;
    ss[d] = sel[b * Ss + d];
    __syncwarp();
    float acc = 0.f;
    const float inv_n = 1.f / 512.f;
    for (int t = 0; t < Tt; t++) {
        g_Kacc[((size_t)b * Tt + t) * DKEY + d] = acc;
        if (t < Ss) acc += g_padkey[((size_t)b * NP1 + ss[t]) * DKEY + d] * inv_n;
    }
}

// ---------------- fused: pre-relu update -> relu -> fc2 -> W_ih gates ------
__global__ __launch_bounds__(256) void k_xg(const float* __restrict__ b2,
                                            const float* __restrict__ W2,
                                            const float* __restrict__ Wih,
                                            const float* __restrict__ bih,
                                            const float* __restrict__ bhh) {
    __shared__ float ka[DKEY];
    __shared__ float xr[DFUNC];
    __shared__ float xs[DKEY];
    int t = blockIdx.x, b = blockIdx.y, j = threadIdx.x;
    if (j < DKEY) ka[j] = g_Kacc[((size_t)b * Tt + t) * DKEY + j];
    __syncthreads();
    float r = g_A0[b * DFUNC + j] + (float)t * g_v[j];
    const float* mr = g_M + j * DKEY;
#pragma unroll
    for (int d = 0; d < DKEY; d++) r += ka[d] * mr[d];
    xr[j] = fmaxf(r, 0.f);
    __syncthreads();
    if (j < DKEY) {
        float a = b2[j];
        const float* w = W2 + j * DFUNC;
#pragma unroll 4
        for (int k = 0; k < DFUNC; k++) a += xr[k] * w[k];
        xs[j] = a;
    }
    __syncthreads();
    if (j < G4) {
        float a = bih[j] + bhh[j];
        const float* w = Wih + j * HH;
#pragma unroll
        for (int c = 0; c < HH; c++) a += xs[c] * w[c];
        g_G[((size_t)b * Tt + t) * G4 + j] = a;
    }
}

// ---------------- LSTM scan (the only truly serial part) -------------------
__global__ __launch_bounds__(128) void k_lstm(const float* __restrict__ Whh) {
    __shared__ float wh[HH * G4];   // [c][g] (transposed for conflict-free read)
    __shared__ float gates[G4];
    __shared__ float hs[HH], cs[HH];
    int b = blockIdx.x, g = threadIdx.x;
    for (int idx = g; idx < G4 * HH; idx += 128) {
        int gg = idx >> 5, cc = idx & 31;
        wh[cc * G4 + gg] = Whh[idx];
    }
    if (g < HH) { hs[g] = 0.f; cs[g] = 0.f; }
    __syncthreads();
    for (int t = 0; t < Tt; t++) {
        float a = g_G[((size_t)b * Tt + t) * G4 + g];
#pragma unroll
        for (int c = 0; c < HH; c++) a += hs[c] * wh[c * G4 + g];
        gates[g] = a;
        __syncthreads();
        if (g < HH) {
            float ig = gates[g], fg = gates[32 + g], gg = gates[64 + g], og = gates[96 + g];
            float si = 1.f / (1.f + expf(-ig));
            float sf = 1.f / (1.f + expf(-fg));
            float so = 1.f / (1.f + expf(-og));
            float cn = sf * cs[g] + si * tanhf(gg);
            cs[g] = cn;
            float hn = so * tanhf(cn);
            hs[g] = hn;
            g_H[((size_t)b * Tt + t) * HH + g] = hn;
        }
        __syncthreads();
    }
}

// ---------------- logits: q[b,t,n] = H[b,t]·key[b,n] - (1-mask_t)*1e9 ------
__global__ __launch_bounds__(128) void k_logits(float* __restrict__ out) {
    __shared__ float hsm[Tt * HH];
    int b = blockIdx.y;
    int n = blockIdx.x * 128 + threadIdx.x;
    for (int i = threadIdx.x; i < Tt * HH; i += 128) hsm[i] = g_H[(size_t)b * Tt * HH + i];
    __syncthreads();
    if (n >= NP1) return;
    float4 key[8];
    const float4* kp = (const float4*)(g_padkey + ((size_t)b * NP1 + n) * DKEY);
#pragma unroll
    for (int i = 0; i < 8; i++) key[i] = kp[i];
    int fs = g_fs[b * NP1 + n];
    float m0 = g_mask0[b * NP1 + n];
    float* ob = out + (size_t)b * Tt * NP1 + n;
    const float4* h4 = (const float4*)hsm;
    for (int t = 0; t < Tt; t++) {
        float acc = 0.f;
#pragma unroll
        for (int q = 0; q < 8; q++) {
            float4 h = h4[t * 8 + q];
            acc += h.x * key[q].x + h.y * key[q].y + h.z * key[q].z + h.w * key[q].w;
        }
        float pen = (m0 != 0.f && t <= fs) ? 0.f : 1e9f;
        ob[(size_t)t * NP1] = acc - pen;
    }
}

// ---------------- final emb = emb0 + Kacc_S @ W_embed^T + S*b_embed --------
__global__ __launch_bounds__(256) void k_embout(const float* __restrict__ emb,
                                                const float* __restrict__ We,
                                                const float* __restrict__ be,
                                                float* __restrict__ out) {
    __shared__ float ka[DKEY];
    int b = blockIdx.x, tid = threadIdx.x;
    if (tid < DKEY) ka[tid] = g_Kacc[((size_t)b * Tt + Ss) * DKEY + tid];
    __syncthreads();
    for (int k = tid; k < DIN; k += 256) {
        float a = emb[(size_t)b * DIN + k] + 32.f * be[k];
        const float* w = We + (size_t)k * DKEY;
#pragma unroll
        for (int d = 0; d < DKEY; d++) a += ka[d] * w[d];
        out[(size_t)(Bq * Tt * NP1) + (size_t)b * DIN + k] = a;
    }
}

extern "C" void kernel_launch(void* const* d_in, const int* in_sizes, int n_in,
                              void* d_out, int out_size) {
    (void)in_sizes; (void)n_in;
    const float* emb    = (const float*)d_in[0];
    const float* tmask  = (const float*)d_in[1];
    const float* avail  = (const float*)d_in[2];
    const float* ent    = (const float*)d_in[3];
    const int*   sel    = (const int*)d_in[4];
    const float* endemb = (const float*)d_in[5];
    const float* Wk  = (const float*)d_in[6];
    const float* bk  = (const float*)d_in[7];
    const float* Wf  = (const float*)d_in[8];
    const float* bf  = (const float*)d_in[9];
    const float* W1  = (const float*)d_in[10];
    const float* b1  = (const float*)d_in[11];
    const float* W2  = (const float*)d_in[12];
    const float* b2  = (const float*)d_in[13];
    const float* We  = (const float*)d_in[14];
    const float* be  = (const float*)d_in[15];
    const float* Wih = (const float*)d_in[16];
    const float* bih = (const float*)d_in[17];
    const float* Whh = (const float*)d_in[18];
    const float* bhh = (const float*)d_in[19];
    float* out = (float*)d_out;

    k_padkey<<<(Bq * Nn) / 64, 256>>>(ent, Wk, bk);
    k_endrow<<<Bq, 32>>>(endemb);
    k_funcembed<<<Bq, 256>>>(tmask, Wf, bf);
    k_A0<<<Bq / 4, 256>>>(emb, W1, b1);
    k_Mv<<<DFUNC, 64>>>(W1, We, be);
    k_maskprep<<<Bq, 256>>>(avail, sel);
    k_gather<<<Bq, 32>>>(sel);
    k_xg<<<dim3(Tt, Bq), 256>>>(b2, W2, Wih, bih, bhh);
    k_lstm<<<Bq, 128>>>(Whh);
    k_logits<<<dim3((NP1 + 127) / 128, Bq), 128>>>(out);
    if (out_size >= Bq * Tt * NP1 + Bq * DIN)
        k_embout<<<Bq, 256>>>(emb, We, be, out);
}

// round 10
// speedup vs baseline: 2.6022x; 2.6022x over previous
#include <cuda_runtime.h>
#include <math.h>

#define Bq 256
#define Nn 512
#define NP1 513
#define Ss 32
#define Tt 33
#define DENT 256
#define DKEY 32
#define DIN 1024
#define DFUNC 256
#define DTYPE 259
#define HH 32
#define G4 128
#define TBT 4

// ---------------- scratch (static device globals; no allocations) ----------
__device__ float g_padkey[Bq * NP1 * DKEY];   // [b][n][k]
__device__ float g_func[Bq * DFUNC];
__device__ float g_A0[Bq * DFUNC];            // emb0@Wfc1^T + b_fc1 + func_embed
__device__ float g_MT[DKEY * DFUNC];          // (W_fc1 @ W_embed)^T : [d][j]
__device__ float g_v[DFUNC];                  // W_fc1 @ b_embed
__device__ float g_mask0[Bq * NP1];
__device__ int   g_fs[Bq * NP1];              // first step n was selected (INT_MAX if never)
__device__ float g_Kacc[Bq * Tt * DKEY];      // inv_n * prefix sum of selected keys
__device__ float g_G[Bq * Tt * G4];           // x@Wih^T + b_ih + b_hh
__device__ float g_H[Bq * Tt * HH];           // h after LSTM update at step t
// transposed weights (coalesced inner loops)
__device__ float g_W1T[DIN * DFUNC];          // [k][j]
__device__ float g_WfT[DTYPE * DFUNC];        // [k][j]
__device__ float g_W2T[DFUNC * DKEY];         // [k][c]
__device__ float g_WihT[HH * G4];             // [c][g]
__device__ float g_WeT[DKEY * DIN];           // [d][k]

// ---------------- generic tiled transpose: in[R][C] -> out[C][R] -----------
__global__ void k_transpose(const float* __restrict__ in, float* __restrict__ out,
                            int R, int C) {
    __shared__ float tile[32][33];
    int c0 = blockIdx.x * 32, r0 = blockIdx.y * 32;
    int x = threadIdx.x, y = threadIdx.y;   // 32 x 8
#pragma unroll
    for (int i = 0; i < 32; i += 8) {
        int r = r0 + y + i, c = c0 + x;
        if (r < R && c < C) tile[y + i][x] = in[(size_t)r * C + c];
    }
    __syncthreads();
#pragma unroll
    for (int i = 0; i < 32; i += 8) {
        int r = r0 + x, c = c0 + y + i;
        if (r < R && c < C) out[(size_t)c * R + r] = tile[x][y + i];
    }
}

// ---------------- pad_key = entity @ W_key^T + b_key -----------------------
__global__ __launch_bounds__(256) void k_padkey(const float* __restrict__ ent,
                                                const float* __restrict__ Wk,
                                                const float* __restrict__ bk) {
    __shared__ float Wt[DENT * DKEY];   // [k][c]
    __shared__ float es[32 * 65];       // [kk][e]
    const int tid = threadIdx.x;
    const int r0 = blockIdx.x * 64;
    for (int idx = tid; idx < DENT * DKEY; idx += 256) {
        int c = idx >> 8, k = idx & 255;
        Wt[k * DKEY + c] = Wk[idx];
    }
    __syncthreads();
    const int e = tid & 63;
    const int c = (tid >> 6) * 8;
    float acc[8];
#pragma unroll
    for (int j = 0; j < 8; j++) acc[j] = 0.f;
    for (int kc = 0; kc < DENT; kc += 32) {
        for (int idx = tid; idx < 64 * 32; idx += 256) {
            int ee = idx >> 5, kk = idx & 31;
            es[kk * 65 + ee] = ent[(size_t)(r0 + ee) * DENT + kc + kk];
        }
        __syncthreads();
#pragma unroll
        for (int kk = 0; kk < 32; kk++) {
            float a = es[kk * 65 + e];
            const float4* w4 = (const float4*)&Wt[(kc + kk) * DKEY + c];
            float4 w0 = w4[0], w1 = w4[1];
            acc[0] += a * w0.x; acc[1] += a * w0.y;
            acc[2] += a * w0.z; acc[3] += a * w0.w;
            acc[4] += a * w1.x; acc[5] += a * w1.y;
            acc[6] += a * w1.z; acc[7] += a * w1.w;
        }
        __syncthreads();
    }
    int r = r0 + e;
    int b = r >> 9;
    size_t off = (size_t)32 * (r + b) + c;   // b*513*32 + n*32 + c
#pragma unroll
    for (int j = 0; j < 8; j++) g_padkey[off + j] = acc[j] + bk[c + j];
}

__global__ void k_endrow(const float* __restrict__ endemb) {
    g_padkey[((size_t)blockIdx.x * NP1 + Nn) * DKEY + threadIdx.x] = endemb[threadIdx.x];
}

// ---------------- func_embed = relu(type_mask @ W_func^T + b_func) ---------
__global__ __launch_bounds__(256) void k_funcembed(const float* __restrict__ tmask,
                                                   const float* __restrict__ bf) {
    __shared__ float ts[DTYPE + 1];
    int b = blockIdx.x, j = threadIdx.x;
    for (int i = j; i < DTYPE; i += 256) ts[i] = tmask[b * DTYPE + i];
    __syncthreads();
    float a0 = 0.f, a1 = 0.f;
    int k = 0;
    for (; k + 1 < DTYPE; k += 2) {
        a0 += ts[k] * g_WfT[k * DFUNC + j];
        a1 += ts[k + 1] * g_WfT[(k + 1) * DFUNC + j];
    }
    if (k < DTYPE) a0 += ts[k] * g_WfT[k * DFUNC + j];
    g_func[b * DFUNC + j] = fmaxf(a0 + a1 + bf[j], 0.f);
}

// ---------------- A0 = emb0 @ W_fc1^T + b_fc1 + func_embed (2 b / block) ---
__global__ __launch_bounds__(256) void k_A0(const float* __restrict__ emb,
                                            const float* __restrict__ b1) {
    __shared__ float es[2 * DIN];
    int b0 = blockIdx.x * 2;
    int j = threadIdx.x;
    for (int i = j; i < 2 * DIN; i += 256) es[i] = emb[(size_t)b0 * DIN + i];
    __syncthreads();
    float a00 = 0.f, a01 = 0.f, a10 = 0.f, a11 = 0.f;
#pragma unroll 8
    for (int k = 0; k < DIN; k += 2) {
        float w0 = g_W1T[k * DFUNC + j];
        float w1 = g_W1T[(k + 1) * DFUNC + j];
        a00 += w0 * es[k];        a01 += w1 * es[k + 1];
        a10 += w0 * es[DIN + k];  a11 += w1 * es[DIN + k + 1];
    }
    float bias = b1[j];
    g_A0[(b0 + 0) * DFUNC + j] = a00 + a01 + bias + g_func[(b0 + 0) * DFUNC + j];
    g_A0[(b0 + 1) * DFUNC + j] = a10 + a11 + bias + g_func[(b0 + 1) * DFUNC + j];
}

// ---------------- MT = (W_fc1 @ W_embed)^T ; v = W_fc1 @ b_embed -----------
__global__ __launch_bounds__(256) void k_Mv(const float* __restrict__ W1,
                                            const float* __restrict__ We,
                                            const float* __restrict__ be) {
    __shared__ float wr[DIN];
    __shared__ float part[256];
    int j = blockIdx.x, tid = threadIdx.x;
    for (int i = tid; i < DIN; i += 256) wr[i] = W1[(size_t)j * DIN + i];
    __syncthreads();
    int d = tid & 31, p = tid >> 5;
    float a = 0.f;
    int k0 = p * 128;
#pragma unroll 4
    for (int k = k0; k < k0 + 128; k++) a += wr[k] * We[k * DKEY + d];
    part[tid] = a;
    __syncthreads();
    if (tid < 32) {
        float s = part[tid];
#pragma unroll
        for (int pp = 1; pp < 8; pp++) s += part[pp * 32 + tid];
        g_MT[tid * DFUNC + j] = s;
        float vp = 0.f;
        for (int k = tid; k < DIN; k += 32) vp += wr[k] * be[k];
#pragma unroll
        for (int o = 16; o; o >>= 1) vp += __shfl_xor_sync(0xffffffffu, vp, o);
        if (tid == 0) g_v[j] = vp;
    }
}

// ---------------- mask0 + first-selection-step per (b,n) -------------------
__global__ __launch_bounds__(256) void k_maskprep(const float* __restrict__ avail,
                                                  const int* __restrict__ sel) {
    __shared__ int ss[Ss];
    int b = blockIdx.x, tid = threadIdx.x;
    if (tid < Ss) ss[tid] = sel[b * Ss + tid];
    __syncthreads();
    for (int n = tid; n < NP1; n += 256) {
        int fs = 0x7FFFFFFF;
#pragma unroll
        for (int s = 0; s < Ss; s++)
            if (ss[s] == n && s < fs) fs = s;
        float m = (n == Nn) ? 1.f : avail[b * Nn + n];
        if (fs < Ss) m = 1.f;
        g_mask0[b * NP1 + n] = m;
        g_fs[b * NP1 + n] = fs;
    }
}

// ---------------- Kacc: prefix sums of selected keys -----------------------
__global__ __launch_bounds__(32) void k_gather(const int* __restrict__ sel) {
    __shared__ int ss[Ss];
    int b = blockIdx.x, d = threadIdx.x;
    ss[d] = sel[b * Ss + d];
    __syncwarp();
    float acc = 0.f;
    const float inv_n = 1.f / 512.f;
    for (int t = 0; t < Tt; t++) {
        g_Kacc[((size_t)b * Tt + t) * DKEY + d] = acc;
        if (t < Ss) acc += g_padkey[((size_t)b * NP1 + ss[t]) * DKEY + d] * inv_n;
    }
}

// ---- fused: pre-relu update -> relu -> fc2 -> W_ih gates (4 t per block) --
__global__ __launch_bounds__(256) void k_xg(const float* __restrict__ b2,
                                            const float* __restrict__ bih,
                                            const float* __restrict__ bhh) {
    __shared__ float ka[TBT][DKEY];
    __shared__ float xr[TBT][DFUNC];
    __shared__ float xs[TBT][DKEY];
    __shared__ float p2[TBT][8][DKEY];
    int t0 = blockIdx.x * TBT, b = blockIdx.y, j = threadIdx.x;
    if (j < TBT * DKEY) {
        int tt = j >> 5, d = j & 31;
        int t = t0 + tt; if (t >= Tt) t = Tt - 1;
        ka[tt][d] = g_Kacc[((size_t)b * Tt + t) * DKEY + d];
    }
    __syncthreads();
    // phase 1: xr[tt][j] = relu(A0 + t*v + Kacc_t . M[j,:])
    float m[DKEY];
#pragma unroll
    for (int d = 0; d < DKEY; d++) m[d] = g_MT[d * DFUNC + j];   // coalesced
    float a0j = g_A0[b * DFUNC + j], vj = g_v[j];
#pragma unroll
    for (int tt = 0; tt < TBT; tt++) {
        float r = a0j + (float)(t0 + tt) * vj;
#pragma unroll
        for (int d = 0; d < DKEY; d++) r += ka[tt][d] * m[d];
        xr[tt][j] = fmaxf(r, 0.f);
    }
    __syncthreads();
    // phase 2: xs[tt][c] = xr[tt,:] . W2[c,:] + b2  (8-way K split, all threads)
    {
        int c = j & 31, p = j >> 5;
        float s[TBT] = {0.f, 0.f, 0.f, 0.f};
        int k0 = p * 32;
#pragma unroll
        for (int k = k0; k < k0 + 32; k++) {
            float w = g_W2T[k * DKEY + c];   // coalesced
#pragma unroll
            for (int tt = 0; tt < TBT; tt++) s[tt] += xr[tt][k] * w;
        }
#pragma unroll
        for (int tt = 0; tt < TBT; tt++) p2[tt][p][c] = s[tt];
    }
    __syncthreads();
    if (j < TBT * DKEY) {
        int tt = j >> 5, d = j & 31;
        float acc = b2[d];
#pragma unroll
        for (int p = 0; p < 8; p++) acc += p2[tt][p][d];
        xs[tt][d] = acc;
    }
    __syncthreads();
    // phase 3: G[tt][g] = xs . W_ih[g,:] + b_ih + b_hh
    if (j < G4) {
        float base = bih[j] + bhh[j];
        float g[TBT] = {base, base, base, base};
#pragma unroll
        for (int c = 0; c < HH; c++) {
            float w = g_WihT[c * G4 + j];   // coalesced
#pragma unroll
            for (int tt = 0; tt < TBT; tt++) g[tt] += xs[tt][c] * w;
        }
#pragma unroll
        for (int tt = 0; tt < TBT; tt++) {
            int t = t0 + tt;
            if (t < Tt) g_G[((size_t)b * Tt + t) * G4 + j] = g[tt];
        }
    }
}

// ---------------- LSTM scan (the only truly serial part) -------------------
__global__ __launch_bounds__(128) void k_lstm(const float* __restrict__ Whh) {
    __shared__ float wh[HH * G4];   // [c][g]
    __shared__ float gates[G4];
    __shared__ float hs[HH], cs[HH];
    int b = blockIdx.x, g = threadIdx.x;
    for (int idx = g; idx < G4 * HH; idx += 128) {
        int gg = idx >> 5, cc = idx & 31;
        wh[cc * G4 + gg] = Whh[idx];
    }
    if (g < HH) { hs[g] = 0.f; cs[g] = 0.f; }
    __syncthreads();
    for (int t = 0; t < Tt; t++) {
        float a = g_G[((size_t)b * Tt + t) * G4 + g];
#pragma unroll
        for (int c = 0; c < HH; c++) a += hs[c] * wh[c * G4 + g];
        gates[g] = a;
        __syncthreads();
        if (g < HH) {
            float ig = gates[g], fg = gates[32 + g], gg = gates[64 + g], og = gates[96 + g];
            float si = 1.f / (1.f + expf(-ig));
            float sf = 1.f / (1.f + expf(-fg));
            float so = 1.f / (1.f + expf(-og));
            float cn = sf * cs[g] + si * tanhf(gg);
            cs[g] = cn;
            float hn = so * tanhf(cn);
            hs[g] = hn;
            g_H[((size_t)b * Tt + t) * HH + g] = hn;
        }
        __syncthreads();
    }
}

// ---------------- logits: q[b,t,n] = H[b,t]·key[b,n] - (1-mask_t)*1e9 ------
__global__ __launch_bounds__(128) void k_logits(float* __restrict__ out) {
    __shared__ float hsm[Tt * HH];
    int b = blockIdx.y;
    int n = blockIdx.x * 128 + threadIdx.x;
    for (int i = threadIdx.x; i < Tt * HH; i += 128) hsm[i] = g_H[(size_t)b * Tt * HH + i];
    __syncthreads();
    if (n >= NP1) return;
    float4 key[8];
    const float4* kp = (const float4*)(g_padkey + ((size_t)b * NP1 + n) * DKEY);
#pragma unroll
    for (int i = 0; i < 8; i++) key[i] = kp[i];
    int fs = g_fs[b * NP1 + n];
    float m0 = g_mask0[b * NP1 + n];
    float* ob = out + (size_t)b * Tt * NP1 + n;
    const float4* h4 = (const float4*)hsm;
    for (int t = 0; t < Tt; t++) {
        float acc[4] = {0.f, 0.f, 0.f, 0.f};
#pragma unroll
        for (int q = 0; q < 8; q++) {
            float4 h = h4[t * 8 + q];
            int s = q & 3;
            acc[s] += h.x * key[q].x + h.y * key[q].y;
            acc[s] += h.z * key[q].z + h.w * key[q].w;
        }
        float dot = (acc[0] + acc[1]) + (acc[2] + acc[3]);
        float pen = (m0 != 0.f && t <= fs) ? 0.f : 1e9f;
        ob[(size_t)t * NP1] = dot - pen;
    }
}

// ---------------- final emb = emb0 + Kacc_S @ W_embed^T + S*b_embed --------
__global__ __launch_bounds__(256) void k_embout(const float* __restrict__ emb,
                                                const float* __restrict__ be,
                                                float* __restrict__ out) {
    __shared__ float ka[DKEY];
    int b = blockIdx.x, tid = threadIdx.x;
    if (tid < DKEY) ka[tid] = g_Kacc[((size_t)b * Tt + Ss) * DKEY + tid];
    __syncthreads();
    for (int k = tid; k < DIN; k += 256) {
        float a = emb[(size_t)b * DIN + k] + 32.f * be[k];
#pragma unroll
        for (int d = 0; d < DKEY; d++) a += ka[d] * g_WeT[d * DIN + k];   // coalesced
        out[(size_t)(Bq * Tt * NP1) + (size_t)b * DIN + k] = a;
    }
}

extern "C" void kernel_launch(void* const* d_in, const int* in_sizes, int n_in,
                              void* d_out, int out_size) {
    (void)in_sizes; (void)n_in;
    const float* emb    = (const float*)d_in[0];
    const float* tmask  = (const float*)d_in[1];
    const float* avail  = (const float*)d_in[2];
    const float* ent    = (const float*)d_in[3];
    const int*   sel    = (const int*)d_in[4];
    const float* endemb = (const float*)d_in[5];
    const float* Wk  = (const float*)d_in[6];
    const float* bk  = (const float*)d_in[7];
    const float* Wf  = (const float*)d_in[8];
    const float* bf  = (const float*)d_in[9];
    const float* W1  = (const float*)d_in[10];
    const float* b1  = (const float*)d_in[11];
    const float* W2  = (const float*)d_in[12];
    const float* b2  = (const float*)d_in[13];
    const float* We  = (const float*)d_in[14];
    const float* be  = (const float*)d_in[15];
    const float* Wih = (const float*)d_in[16];
    const float* bih = (const float*)d_in[17];
    const float* Whh = (const float*)d_in[18];
    const float* bhh = (const float*)d_in[19];
    float* out = (float*)d_out;

    float* pW1T;  cudaGetSymbolAddress((void**)&pW1T,  g_W1T);
    float* pWfT;  cudaGetSymbolAddress((void**)&pWfT,  g_WfT);
    float* pW2T;  cudaGetSymbolAddress((void**)&pW2T,  g_W2T);
    float* pWihT; cudaGetSymbolAddress((void**)&pWihT, g_WihT);
    float* pWeT;  cudaGetSymbolAddress((void**)&pWeT,  g_WeT);

    dim3 tb(32, 8);
    k_transpose<<<dim3((DIN  + 31) / 32, (DFUNC + 31) / 32), tb>>>(W1,  pW1T,  DFUNC, DIN);
    k_transpose<<<dim3((DTYPE+ 31) / 32, (DFUNC + 31) / 32), tb>>>(Wf,  pWfT,  DFUNC, DTYPE);
    k_transpose<<<dim3((DFUNC+ 31) / 32, (DKEY  + 31) / 32), tb>>>(W2,  pW2T,  DKEY,  DFUNC);
    k_transpose<<<dim3((HH   + 31) / 32, (G4    + 31) / 32), tb>>>(Wih, pWihT, G4,    HH);
    k_transpose<<<dim3((DKEY + 31) / 32, (DIN   + 31) / 32), tb>>>(We,  pWeT,  DIN,   DKEY);

    k_padkey<<<(Bq * Nn) / 64, 256>>>(ent, Wk, bk);
    k_endrow<<<Bq, 32>>>(endemb);
    k_funcembed<<<Bq, 256>>>(tmask, bf);
    k_A0<<<Bq / 2, 256>>>(emb, b1);
    k_Mv<<<DFUNC, 256>>>(W1, We, be);
    k_maskprep<<<Bq, 256>>>(avail, sel);
    k_gather<<<Bq, 32>>>(sel);
    k_xg<<<dim3((Tt + TBT - 1) / TBT, Bq), 256>>>(b2, bih, bhh);
    k_lstm<<<Bq, 128>>>(Whh);
    k_logits<<<dim3((NP1 + 127) / 128, Bq), 128>>>(out);
    if (out_size >= Bq * Tt * NP1 + Bq * DIN)
        k_embout<<<Bq, 256>>>(emb, be, out);
}

// round 11
// speedup vs baseline: 2.8373x; 1.0903x over previous
#include <cuda_runtime.h>
#include <math.h>

#define Bq 256
#define Nn 512
#define NP1 513
#define Ss 32
#define Tt 33
#define DENT 256
#define DKEY 32
#define DIN 1024
#define DFUNC 256
#define DTYPE 259
#define HH 32
#define G4 128
#define TBT 4

typedef unsigned long long ull;

__device__ __forceinline__ ull pack2(float x, float y) {
    ull r; asm("mov.b64 %0, {%1, %2};" : "=l"(r) : "f"(x), "f"(y)); return r;
}
__device__ __forceinline__ float2 unpack2(ull v) {
    float2 r; asm("mov.b64 {%0, %1}, %2;" : "=f"(r.x), "=f"(r.y) : "l"(v)); return r;
}
#define FMA2(acc, a, b) asm("fma.rn.f32x2 %0, %1, %2, %0;" : "+l"(acc) : "l"(a), "l"(b))

// ---------------- scratch ---------------------------------------------------
__device__ float g_padkey[Bq * NP1 * DKEY];   // [b][n][k]
__device__ float g_func[Bq * DFUNC];
__device__ float g_A0[Bq * DFUNC];
__device__ float g_MT[DKEY * DFUNC];          // (W_fc1 @ W_embed)^T : [d][j]
__device__ float g_v[DFUNC];
__device__ float g_mask0[Bq * NP1];
__device__ int   g_fs[Bq * NP1];
__device__ float g_Kacc[Bq * Tt * DKEY];
__device__ float g_G[Bq * Tt * G4];
__device__ float g_H[Bq * Tt * HH];
__device__ float g_W1T[DIN * DFUNC];
__device__ float g_WfT[DTYPE * DFUNC];
__device__ float g_W2T[DFUNC * DKEY];
__device__ float g_WihT[HH * G4];
__device__ float g_WeT[DKEY * DIN];

// ---------------- one fused transpose kernel (5 matrices) -------------------
__global__ __launch_bounds__(256) void k_transpose_all(const float* __restrict__ W1,
                                                       const float* __restrict__ Wf,
                                                       const float* __restrict__ W2,
                                                       const float* __restrict__ Wih,
                                                       const float* __restrict__ We) {
    __shared__ float tile[32][33];
    int bid = blockIdx.x;
    const float* in; float* out; int R, C, bx, by;
    if (bid < 256)      { in = W1;  out = g_W1T;  R = DFUNC; C = DIN;   bx = bid & 31; by = bid >> 5; }
    else if (bid < 328) { int t = bid - 256; in = Wf;  out = g_WfT;  R = DFUNC; C = DTYPE; bx = t % 9; by = t / 9; }
    else if (bid < 336) { int t = bid - 328; in = W2;  out = g_W2T;  R = DKEY;  C = DFUNC; bx = t; by = 0; }
    else if (bid < 340) { int t = bid - 336; in = Wih; out = g_WihT; R = G4;    C = HH;    bx = 0; by = t; }
    else                { int t = bid - 340; in = We;  out = g_WeT;  R = DIN;   C = DKEY;  bx = 0; by = t; }
    int c0 = bx * 32, r0 = by * 32;
    int x = threadIdx.x & 31, y = threadIdx.x >> 5;
#pragma unroll
    for (int i = 0; i < 32; i += 8) {
        int r = r0 + y + i, c = c0 + x;
        if (r < R && c < C) tile[y + i][x] = in[(size_t)r * C + c];
    }
    __syncthreads();
#pragma unroll
    for (int i = 0; i < 32; i += 8) {
        int r = r0 + x, c = c0 + y + i;
        if (r < R && c < C) out[(size_t)c * R + r] = tile[x][y + i];
    }
}

// ---------------- pad_key = entity @ W_key^T + b_key (f32x2, 128-row tiles) -
__global__ __launch_bounds__(256) void k_padkey(const float* __restrict__ ent,
                                                const float* __restrict__ Wk,
                                                const float* __restrict__ bk) {
    __shared__ float Wtc[32][34];      // [kk][c], 8B-aligned rows (34 even)
    __shared__ float es[32][129];      // [kk][row], stride 129 -> conflict-free
    const int tid = threadIdx.x;
    const int r0 = blockIdx.x * 128;
    const int e = tid & 63;
    const int c = (tid >> 6) << 3;
    ull acc0[4], acc1[4];
#pragma unroll
    for (int q = 0; q < 4; q++) { acc0[q] = 0ull; acc1[q] = 0ull; }
    for (int kc = 0; kc < DENT; kc += 32) {
        __syncthreads();
        for (int idx = tid; idx < 32 * 32; idx += 256) {
            int cc = idx >> 5, kk = idx & 31;
            Wtc[kk][cc] = Wk[cc * DENT + kc + kk];       // coalesced over kk
        }
        for (int idx = tid; idx < 128 * 32; idx += 256) {
            int ee = idx >> 5, kk = idx & 31;
            es[kk][ee] = ent[(size_t)(r0 + ee) * DENT + kc + kk];
        }
        __syncthreads();
#pragma unroll
        for (int kk = 0; kk < 32; kk++) {
            float a0 = es[kk][e], a1 = es[kk][e + 64];
            ull p0 = pack2(a0, a0), p1 = pack2(a1, a1);
            const ull* w2 = (const ull*)&Wtc[kk][c];
            ull w01 = w2[0], w23 = w2[1], w45 = w2[2], w67 = w2[3];
            FMA2(acc0[0], p0, w01); FMA2(acc0[1], p0, w23);
            FMA2(acc0[2], p0, w45); FMA2(acc0[3], p0, w67);
            FMA2(acc1[0], p1, w01); FMA2(acc1[1], p1, w23);
            FMA2(acc1[2], p1, w45); FMA2(acc1[3], p1, w67);
        }
    }
    int r = r0 + e;
    int b = r >> 9;                      // 128-row tile never crosses a batch row
    size_t off0 = (size_t)32 * (r + b) + c;
    size_t off1 = (size_t)32 * (r + 64 + b) + c;
#pragma unroll
    for (int q = 0; q < 4; q++) {
        float2 u0 = unpack2(acc0[q]), u1 = unpack2(acc1[q]);
        float bk0 = bk[c + 2 * q], bk1 = bk[c + 2 * q + 1];
        g_padkey[off0 + 2 * q] = u0.x + bk0; g_padkey[off0 + 2 * q + 1] = u0.y + bk1;
        g_padkey[off1 + 2 * q] = u1.x + bk0; g_padkey[off1 + 2 * q + 1] = u1.y + bk1;
    }
}

// ---------------- func_embed, 4 batch rows / block --------------------------
__global__ __launch_bounds__(256) void k_funcembed(const float* __restrict__ tmask,
                                                   const float* __restrict__ bf) {
    __shared__ float ts[4][DTYPE + 1];
    int b0 = blockIdx.x * 4, j = threadIdx.x;
#pragma unroll
    for (int bb = 0; bb < 4; bb++)
        for (int i = j; i < DTYPE; i += 256) ts[bb][i] = tmask[(size_t)(b0 + bb) * DTYPE + i];
    __syncthreads();
    float a0 = 0.f, a1 = 0.f, a2 = 0.f, a3 = 0.f;
#pragma unroll 4
    for (int k = 0; k < DTYPE; k++) {
        float w = g_WfT[k * DFUNC + j];
        a0 += ts[0][k] * w; a1 += ts[1][k] * w;
        a2 += ts[2][k] * w; a3 += ts[3][k] * w;
    }
    float bias = bf[j];
    g_func[(b0 + 0) * DFUNC + j] = fmaxf(a0 + bias, 0.f);
    g_func[(b0 + 1) * DFUNC + j] = fmaxf(a1 + bias, 0.f);
    g_func[(b0 + 2) * DFUNC + j] = fmaxf(a2 + bias, 0.f);
    g_func[(b0 + 3) * DFUNC + j] = fmaxf(a3 + bias, 0.f);
}

// ---------------- A0, 4 rows / block, interleaved smem + f32x2 --------------
__global__ __launch_bounds__(256) void k_A0(const float* __restrict__ emb,
                                            const float* __restrict__ b1) {
    __shared__ float esi[DIN * 4];     // [k][r]
    int b0 = blockIdx.x * 4, j = threadIdx.x;
    for (int idx = j; idx < 4 * DIN; idx += 256) {
        int r = idx >> 10, k = idx & 1023;
        esi[k * 4 + r] = emb[(size_t)(b0 + r) * DIN + k];
    }
    __syncthreads();
    ull a01 = 0ull, a23 = 0ull;
#pragma unroll 8
    for (int k = 0; k < DIN; k++) {
        float w = g_W1T[k * DFUNC + j];
        ull wp = pack2(w, w);
        const ull* ep = (const ull*)&esi[k * 4];
        FMA2(a01, wp, ep[0]);
        FMA2(a23, wp, ep[1]);
    }
    float2 u01 = unpack2(a01), u23 = unpack2(a23);
    float bias = b1[j];
    g_A0[(b0 + 0) * DFUNC + j] = u01.x + bias + g_func[(b0 + 0) * DFUNC + j];
    g_A0[(b0 + 1) * DFUNC + j] = u01.y + bias + g_func[(b0 + 1) * DFUNC + j];
    g_A0[(b0 + 2) * DFUNC + j] = u23.x + bias + g_func[(b0 + 2) * DFUNC + j];
    g_A0[(b0 + 3) * DFUNC + j] = u23.y + bias + g_func[(b0 + 3) * DFUNC + j];
}

// ---------------- MT = (W_fc1 @ W_embed)^T ; v = W_fc1 @ b_embed ------------
__global__ __launch_bounds__(256) void k_Mv(const float* __restrict__ W1,
                                            const float* __restrict__ We,
                                            const float* __restrict__ be) {
    __shared__ float wr[DIN];
    __shared__ float part[256];
    int j = blockIdx.x, tid = threadIdx.x;
    for (int i = tid; i < DIN; i += 256) wr[i] = W1[(size_t)j * DIN + i];
    __syncthreads();
    int d = tid & 31, p = tid >> 5;
    float a = 0.f;
    int k0 = p * 128;
#pragma unroll 4
    for (int k = k0; k < k0 + 128; k++) a += wr[k] * We[k * DKEY + d];
    part[tid] = a;
    __syncthreads();
    if (tid < 32) {
        float s = part[tid];
#pragma unroll
        for (int pp = 1; pp < 8; pp++) s += part[pp * 32 + tid];
        g_MT[tid * DFUNC + j] = s;
        float vp = 0.f;
        for (int k = tid; k < DIN; k += 32) vp += wr[k] * be[k];
#pragma unroll
        for (int o = 16; o; o >>= 1) vp += __shfl_xor_sync(0xffffffffu, vp, o);
        if (tid == 0) g_v[j] = vp;
    }
}

// ---------------- prep: end-row + mask0/fs + Kacc prefix sums ---------------
__global__ __launch_bounds__(256) void k_prep(const float* __restrict__ avail,
                                              const int* __restrict__ sel,
                                              const float* __restrict__ endemb) {
    __shared__ int ss[Ss];
    int b = blockIdx.x, tid = threadIdx.x;
    if (tid < Ss) ss[tid] = sel[b * Ss + tid];
    if (tid < DKEY) g_padkey[((size_t)b * NP1 + Nn) * DKEY + tid] = endemb[tid];
    __syncthreads();
    for (int n = tid; n < NP1; n += 256) {
        int fs = 0x7FFFFFFF;
#pragma unroll
        for (int s = 0; s < Ss; s++)
            if (ss[s] == n && s < fs) fs = s;
        float m = (n == Nn) ? 1.f : avail[b * Nn + n];
        if (fs < Ss) m = 1.f;
        g_mask0[b * NP1 + n] = m;
        g_fs[b * NP1 + n] = fs;
    }
    if (tid < 32) {
        int d = tid;
        float acc = 0.f;
        const float inv_n = 1.f / 512.f;
        for (int t = 0; t < Tt; t++) {
            g_Kacc[((size_t)b * Tt + t) * DKEY + d] = acc;
            if (t < Ss) acc += g_padkey[((size_t)b * NP1 + ss[t]) * DKEY + d] * inv_n;
        }
    }
}

// ---- xg: one block per batch row, all 33 steps, weights resident ----------
__global__ __launch_bounds__(256) void k_xg(const float* __restrict__ b2,
                                            const float* __restrict__ bih,
                                            const float* __restrict__ bhh) {
    __shared__ float W2s[DFUNC * DKEY];    // [k][c], 32KB
    __shared__ float kas[Tt * DKEY];       // [t][d]
    __shared__ float xrT[DFUNC * TBT];     // [k][tt]
    __shared__ float xsT[DKEY * TBT];      // [c][tt]
    __shared__ float p2[8][DKEY * TBT];    // [p][c*4+tt]
    int b = blockIdx.x, j = threadIdx.x;
    for (int idx = j; idx < DFUNC * DKEY; idx += 256) W2s[idx] = g_W2T[idx];
    for (int idx = j; idx < Tt * DKEY; idx += 256) kas[idx] = g_Kacc[(size_t)b * Tt * DKEY + idx];
    float a0j = g_A0[b * DFUNC + j], vj = g_v[j];
    ull m2[16];
#pragma unroll
    for (int d = 0; d < 16; d++)
        m2[d] = pack2(g_MT[(2 * d) * DFUNC + j], g_MT[(2 * d + 1) * DFUNC + j]);
    float base_ih = (j < G4) ? (bih[j] + bhh[j]) : 0.f;
    __syncthreads();
    for (int t0 = 0; t0 < Tt; t0 += TBT) {
        // phase 1: xrT[j][tt] = relu(A0 + t*v + Kacc_t . M[j,:])
        float rr[TBT];
#pragma unroll
        for (int tt = 0; tt < TBT; tt++) {
            int t = t0 + tt;
            float r = 0.f;
            if (t < Tt) {
                ull acc = 0ull;
                const ull* ka2 = (const ull*)&kas[t * DKEY];
#pragma unroll
                for (int d = 0; d < 16; d++) FMA2(acc, m2[d], ka2[d]);
                float2 u = unpack2(acc);
                r = fmaxf(a0j + (float)t * vj + u.x + u.y, 0.f);
            }
            rr[tt] = r;
        }
        {
            ull* xw = (ull*)&xrT[j * TBT];
            xw[0] = pack2(rr[0], rr[1]);
            xw[1] = pack2(rr[2], rr[3]);
        }
        __syncthreads();
        // phase 2: xs[c][tt] = sum_k xr[k][tt] * W2T[k][c]  (8-way K split)
        {
            int c = j & 31, p = j >> 5, k0 = p * 32;
            ull s01 = 0ull, s23 = 0ull;
#pragma unroll
            for (int k = k0; k < k0 + 32; k++) {
                float w = W2s[k * DKEY + c];
                ull wp = pack2(w, w);
                const ull* xp = (const ull*)&xrT[k * TBT];
                FMA2(s01, wp, xp[0]); FMA2(s23, wp, xp[1]);
            }
            ull* pp = (ull*)&p2[p][c * TBT];
            pp[0] = s01; pp[1] = s23;
        }
        __syncthreads();
        if (j < DKEY * TBT) {
            int c = j >> 2, tt = j & 3;
            float acc = b2[c];
#pragma unroll
            for (int p = 0; p < 8; p++) acc += p2[p][c * TBT + tt];
            xsT[c * TBT + tt] = acc;
        }
        __syncthreads();
        // phase 3: G[t][g] = xs . Wih[g,:] + b_ih + b_hh
        if (j < G4) {
            ull g01 = pack2(base_ih, base_ih), g23 = g01;
#pragma unroll
            for (int c = 0; c < HH; c++) {
                float w = g_WihT[c * G4 + j];
                ull wp = pack2(w, w);
                const ull* xp = (const ull*)&xsT[c * TBT];
                FMA2(g01, wp, xp[0]); FMA2(g23, wp, xp[1]);
            }
            float2 u01 = unpack2(g01), u23 = unpack2(g23);
            float gv[TBT] = {u01.x, u01.y, u23.x, u23.y};
#pragma unroll
            for (int tt = 0; tt < TBT; tt++) {
                int t = t0 + tt;
                if (t < Tt) g_G[((size_t)b * Tt + t) * G4 + j] = gv[tt];
            }
        }
        __syncthreads();
    }
}

// ---------------- LSTM scan -------------------------------------------------
__global__ __launch_bounds__(128) void k_lstm(const float* __restrict__ Whh) {
    __shared__ float wh[HH * G4];   // [c][g]
    __shared__ float gates[G4];
    __shared__ float hs[HH], cs[HH];
    int b = blockIdx.x, g = threadIdx.x;
    for (int idx = g; idx < G4 * HH; idx += 128) {
        int gg = idx >> 5, cc = idx & 31;
        wh[cc * G4 + gg] = Whh[idx];
    }
    if (g < HH) { hs[g] = 0.f; cs[g] = 0.f; }
    __syncthreads();
    for (int t = 0; t < Tt; t++) {
        float a = g_G[((size_t)b * Tt + t) * G4 + g];
#pragma unroll
        for (int c = 0; c < HH; c++) a += hs[c] * wh[c * G4 + g];
        gates[g] = a;
        __syncthreads();
        if (g < HH) {
            float ig = gates[g], fg = gates[32 + g], gg = gates[64 + g], og = gates[96 + g];
            float si = 1.f / (1.f + expf(-ig));
            float sf = 1.f / (1.f + expf(-fg));
            float so = 1.f / (1.f + expf(-og));
            float cn = sf * cs[g] + si * tanhf(gg);
            cs[g] = cn;
            float hn = so * tanhf(cn);
            hs[g] = hn;
            g_H[((size_t)b * Tt + t) * HH + g] = hn;
        }
        __syncthreads();
    }
}

// ---------------- logits (f32x2) -------------------------------------------
__global__ __launch_bounds__(128) void k_logits(float* __restrict__ out) {
    __shared__ float hsm[Tt * HH];
    int b = blockIdx.y;
    int n = blockIdx.x * 128 + threadIdx.x;
    for (int i = threadIdx.x; i < Tt * HH; i += 128) hsm[i] = g_H[(size_t)b * Tt * HH + i];
    __syncthreads();
    if (n >= NP1) return;
    ull key2[16];
    const ull* kp = (const ull*)(g_padkey + ((size_t)b * NP1 + n) * DKEY);
#pragma unroll
    for (int q = 0; q < 16; q++) key2[q] = kp[q];
    int fs = g_fs[b * NP1 + n];
    float m0 = g_mask0[b * NP1 + n];
    float* ob = out + (size_t)b * Tt * NP1 + n;
    const ull* h2 = (const ull*)hsm;
    for (int t = 0; t < Tt; t++) {
        ull a0 = 0ull, a1 = 0ull, a2 = 0ull, a3 = 0ull;
#pragma unroll
        for (int q = 0; q < 16; q += 4) {
            FMA2(a0, h2[t * 16 + q + 0], key2[q + 0]);
            FMA2(a1, h2[t * 16 + q + 1], key2[q + 1]);
            FMA2(a2, h2[t * 16 + q + 2], key2[q + 2]);
            FMA2(a3, h2[t * 16 + q + 3], key2[q + 3]);
        }
        float2 u0 = unpack2(a0), u1 = unpack2(a1), u2 = unpack2(a2), u3 = unpack2(a3);
        float dot = ((u0.x + u0.y) + (u1.x + u1.y)) + ((u2.x + u2.y) + (u3.x + u3.y));
        float pen = (m0 != 0.f && t <= fs) ? 0.f : 1e9f;
        ob[(size_t)t * NP1] = dot - pen;
    }
}

// ---------------- final emb, 4 rows / block ---------------------------------
__global__ __launch_bounds__(256) void k_embout(const float* __restrict__ emb,
                                                const float* __restrict__ be,
                                                float* __restrict__ out) {
    __shared__ float ka[4][DKEY];
    int b0 = blockIdx.x * 4, tid = threadIdx.x;
    if (tid < 4 * DKEY) {
        int r = tid >> 5, d = tid & 31;
        ka[r][d] = g_Kacc[((size_t)(b0 + r) * Tt + Ss) * DKEY + d];
    }
    __syncthreads();
    for (int k = tid; k < DIN; k += 256) {
        float base = 32.f * be[k];
        float a0 = emb[(size_t)(b0 + 0) * DIN + k] + base;
        float a1 = emb[(size_t)(b0 + 1) * DIN + k] + base;
        float a2 = emb[(size_t)(b0 + 2) * DIN + k] + base;
        float a3 = emb[(size_t)(b0 + 3) * DIN + k] + base;
#pragma unroll
        for (int d = 0; d < DKEY; d++) {
            float w = g_WeT[d * DIN + k];
            a0 += ka[0][d] * w; a1 += ka[1][d] * w;
            a2 += ka[2][d] * w; a3 += ka[3][d] * w;
        }
        size_t ob = (size_t)(Bq * Tt * NP1);
        out[ob + (size_t)(b0 + 0) * DIN + k] = a0;
        out[ob + (size_t)(b0 + 1) * DIN + k] = a1;
        out[ob + (size_t)(b0 + 2) * DIN + k] = a2;
        out[ob + (size_t)(b0 + 3) * DIN + k] = a3;
    }
}

extern "C" void kernel_launch(void* const* d_in, const int* in_sizes, int n_in,
                              void* d_out, int out_size) {
    (void)in_sizes; (void)n_in;
    const float* emb    = (const float*)d_in[0];
    const float* tmask  = (const float*)d_in[1];
    const float* avail  = (const float*)d_in[2];
    const float* ent    = (const float*)d_in[3];
    const int*   sel    = (const int*)d_in[4];
    const float* endemb = (const float*)d_in[5];
    const float* Wk  = (const float*)d_in[6];
    const float* bk  = (const float*)d_in[7];
    const float* Wf  = (const float*)d_in[8];
    const float* bf  = (const float*)d_in[9];
    const float* W1  = (const float*)d_in[10];
    const float* b1  = (const float*)d_in[11];
    const float* W2  = (const float*)d_in[12];
    const float* b2  = (const float*)d_in[13];
    const float* We  = (const float*)d_in[14];
    const float* be  = (const float*)d_in[15];
    const float* Wih = (const float*)d_in[16];
    const float* bih = (const float*)d_in[17];
    const float* Whh = (const float*)d_in[18];
    const float* bhh = (const float*)d_in[19];
    float* out = (float*)d_out;

    k_transpose_all<<<372, 256>>>(W1, Wf, W2, Wih, We);
    k_padkey<<<(Bq * Nn) / 128, 256>>>(ent, Wk, bk);
    k_funcembed<<<Bq / 4, 256>>>(tmask, bf);
    k_A0<<<Bq / 4, 256>>>(emb, b1);
    k_Mv<<<DFUNC, 256>>>(W1, We, be);
    k_prep<<<Bq, 256>>>(avail, sel, endemb);
    k_xg<<<Bq, 256>>>(b2, bih, bhh);
    k_lstm<<<Bq, 128>>>(Whh);
    k_logits<<<dim3((NP1 + 127) / 128, Bq), 128>>>(out);
    if (out_size >= Bq * Tt * NP1 + Bq * DIN)
        k_embout<<<Bq / 4, 256>>>(emb, be, out);
}

// round 15
// speedup vs baseline: 3.7634x; 1.3264x over previous
#include <cuda_runtime.h>
#include <math.h>

#define Bq 256
#define Nn 512
#define NP1 513
#define Ss 32
#define Tt 33
#define DENT 256
#define DKEY 32
#define DIN 1024
#define DFUNC 256
#define DTYPE 259
#define HH 32
#define G4 128
#define TBT 4
#define KSPLIT 8

typedef unsigned long long ull;

__device__ __forceinline__ ull pack2(float x, float y) {
    ull r; asm("mov.b64 %0, {%1, %2};" : "=l"(r) : "f"(x), "f"(y)); return r;
}
__device__ __forceinline__ float2 unpack2(ull v) {
    float2 r; asm("mov.b64 {%0, %1}, %2;" : "=f"(r.x), "=f"(r.y) : "l"(v)); return r;
}
#define FMA2(acc, a, b) asm("fma.rn.f32x2 %0, %1, %2, %0;" : "+l"(acc) : "l"(a), "l"(b))

// ---------------- scratch ---------------------------------------------------
__device__ float g_padkey[Bq * NP1 * DKEY];   // [b][n][k]
__device__ float g_A0base[Bq * DFUNC];        // relu(func)+b1
__device__ float g_A0p[KSPLIT * Bq * DFUNC];  // split-K partials
__device__ float g_A0[Bq * DFUNC];
__device__ float g_MT[DKEY * DFUNC];
__device__ float g_v[DFUNC];
__device__ float g_mask0[Bq * NP1];
__device__ int   g_fs[Bq * NP1];
__device__ float g_Kacc[Bq * Tt * DKEY];
__device__ float g_G[Bq * Tt * G4];
__device__ float g_H[Bq * Tt * HH];
__device__ float g_W1T[DIN * DFUNC];
__device__ float g_WfT[DTYPE * DFUNC];
__device__ float g_W2T[DFUNC * DKEY];
__device__ float g_WihT[HH * G4];
__device__ float g_WeT[DKEY * DIN];

// ---------------- one fused transpose kernel (5 matrices) -------------------
__global__ __launch_bounds__(256) void k_transpose_all(const float* __restrict__ W1,
                                                       const float* __restrict__ Wf,
                                                       const float* __restrict__ W2,
                                                       const float* __restrict__ Wih,
                                                       const float* __restrict__ We) {
    __shared__ float tile[32][33];
    int bid = blockIdx.x;
    const float* in; float* out; int R, C, bx, by;
    if (bid < 256)      { in = W1;  out = g_W1T;  R = DFUNC; C = DIN;   bx = bid & 31; by = bid >> 5; }
    else if (bid < 328) { int t = bid - 256; in = Wf;  out = g_WfT;  R = DFUNC; C = DTYPE; bx = t % 9; by = t / 9; }
    else if (bid < 336) { int t = bid - 328; in = W2;  out = g_W2T;  R = DKEY;  C = DFUNC; bx = t; by = 0; }
    else if (bid < 340) { int t = bid - 336; in = Wih; out = g_WihT; R = G4;    C = HH;    bx = 0; by = t; }
    else                { int t = bid - 340; in = We;  out = g_WeT;  R = DIN;   C = DKEY;  bx = 0; by = t; }
    int c0 = bx * 32, r0 = by * 32;
    int x = threadIdx.x & 31, y = threadIdx.x >> 5;
#pragma unroll
    for (int i = 0; i < 32; i += 8) {
        int r = r0 + y + i, c = c0 + x;
        if (r < R && c < C) tile[y + i][x] = in[(size_t)r * C + c];
    }
    __syncthreads();
#pragma unroll
    for (int i = 0; i < 32; i += 8) {
        int r = r0 + x, c = c0 + y + i;
        if (r < R && c < C) out[(size_t)c * R + r] = tile[x][y + i];
    }
}

// ---------------- pad_key (f32x2, 128-row tiles) ----------------------------
__global__ __launch_bounds__(256) void k_padkey(const float* __restrict__ ent,
                                                const float* __restrict__ Wk,
                                                const float* __restrict__ bk) {
    __shared__ __align__(16) float Wtc[32][34];
    __shared__ __align__(16) float es[32][129];
    const int tid = threadIdx.x;
    const int r0 = blockIdx.x * 128;
    const int e = tid & 63;
    const int c = (tid >> 6) << 3;
    ull acc0[4], acc1[4];
#pragma unroll
    for (int q = 0; q < 4; q++) { acc0[q] = 0ull; acc1[q] = 0ull; }
    for (int kc = 0; kc < DENT; kc += 32) {
        __syncthreads();
        for (int idx = tid; idx < 32 * 32; idx += 256) {
            int cc = idx >> 5, kk = idx & 31;
            Wtc[kk][cc] = Wk[cc * DENT + kc + kk];
        }
        for (int idx = tid; idx < 128 * 32; idx += 256) {
            int ee = idx >> 5, kk = idx & 31;
            es[kk][ee] = ent[(size_t)(r0 + ee) * DENT + kc + kk];
        }
        __syncthreads();
#pragma unroll
        for (int kk = 0; kk < 32; kk++) {
            float a0 = es[kk][e], a1 = es[kk][e + 64];
            ull p0 = pack2(a0, a0), p1 = pack2(a1, a1);
            const ull* w2 = (const ull*)&Wtc[kk][c];
            ull w01 = w2[0], w23 = w2[1], w45 = w2[2], w67 = w2[3];
            FMA2(acc0[0], p0, w01); FMA2(acc0[1], p0, w23);
            FMA2(acc0[2], p0, w45); FMA2(acc0[3], p0, w67);
            FMA2(acc1[0], p1, w01); FMA2(acc1[1], p1, w23);
            FMA2(acc1[2], p1, w45); FMA2(acc1[3], p1, w67);
        }
    }
    int r = r0 + e;
    int b = r >> 9;
    size_t off0 = (size_t)32 * (r + b) + c;
    size_t off1 = (size_t)32 * (r + 64 + b) + c;
#pragma unroll
    for (int q = 0; q < 4; q++) {
        float2 u0 = unpack2(acc0[q]), u1 = unpack2(acc1[q]);
        float bk0 = bk[c + 2 * q], bk1 = bk[c + 2 * q + 1];
        g_padkey[off0 + 2 * q] = u0.x + bk0; g_padkey[off0 + 2 * q + 1] = u0.y + bk1;
        g_padkey[off1 + 2 * q] = u1.x + bk0; g_padkey[off1 + 2 * q + 1] = u1.y + bk1;
    }
}

// ---------------- A0base = relu(tmask@WfT + bf) + b1  (4 rows, batched LDG) -
__global__ __launch_bounds__(256) void k_funcembed(const float* __restrict__ tmask,
                                                   const float* __restrict__ bf,
                                                   const float* __restrict__ b1) {
    __shared__ float ts[4][DTYPE + 1];
    int b0 = blockIdx.x * 4, j = threadIdx.x;
#pragma unroll
    for (int bb = 0; bb < 4; bb++)
        for (int i = j; i < DTYPE; i += 256) ts[bb][i] = tmask[(size_t)(b0 + bb) * DTYPE + i];
    __syncthreads();
    float a0 = 0.f, a1 = 0.f, a2 = 0.f, a3 = 0.f;
    int k = 0;
    for (; k + 8 <= DTYPE; k += 8) {
        float w[8];
#pragma unroll
        for (int u = 0; u < 8; u++) w[u] = g_WfT[(k + u) * DFUNC + j];
#pragma unroll
        for (int u = 0; u < 8; u++) {
            a0 += ts[0][k + u] * w[u]; a1 += ts[1][k + u] * w[u];
            a2 += ts[2][k + u] * w[u]; a3 += ts[3][k + u] * w[u];
        }
    }
    for (; k < DTYPE; k++) {
        float w = g_WfT[k * DFUNC + j];
        a0 += ts[0][k] * w; a1 += ts[1][k] * w;
        a2 += ts[2][k] * w; a3 += ts[3][k] * w;
    }
    float bias = bf[j], add = b1[j];
    g_A0base[(b0 + 0) * DFUNC + j] = fmaxf(a0 + bias, 0.f) + add;
    g_A0base[(b0 + 1) * DFUNC + j] = fmaxf(a1 + bias, 0.f) + add;
    g_A0base[(b0 + 2) * DFUNC + j] = fmaxf(a2 + bias, 0.f) + add;
    g_A0base[(b0 + 3) * DFUNC + j] = fmaxf(a3 + bias, 0.f) + add;
}

// ---------------- A0 partials: split-K GEMM, 8 rows x 256 out, K-chunk 128 --
__global__ __launch_bounds__(256) void k_A0p(const float* __restrict__ emb) {
    __shared__ __align__(16) float esi[128 * 8];   // [k][r]
    int ks = blockIdx.x, bg = blockIdx.y;
    int b0 = bg * 8, k0 = ks * 128;
    int j = threadIdx.x;
    for (int idx = j; idx < 1024; idx += 256) {
        int r = idx >> 7, k = idx & 127;
        esi[k * 8 + r] = emb[(size_t)(b0 + r) * DIN + k0 + k];
    }
    __syncthreads();
    ull a01 = 0ull, a23 = 0ull, a45 = 0ull, a67 = 0ull;
    for (int k = 0; k < 128; k += 8) {
        float w[8];
#pragma unroll
        for (int u = 0; u < 8; u++) w[u] = g_W1T[(size_t)(k0 + k + u) * DFUNC + j];
#pragma unroll
        for (int u = 0; u < 8; u++) {
            ull wp = pack2(w[u], w[u]);
            const ull* ep = (const ull*)&esi[(k + u) * 8];
            FMA2(a01, wp, ep[0]); FMA2(a23, wp, ep[1]);
            FMA2(a45, wp, ep[2]); FMA2(a67, wp, ep[3]);
        }
    }
    float2 u01 = unpack2(a01), u23 = unpack2(a23), u45 = unpack2(a45), u67 = unpack2(a67);
    float* o = g_A0p + ((size_t)ks * Bq + b0) * DFUNC + j;
    o[0 * DFUNC] = u01.x; o[1 * DFUNC] = u01.y;
    o[2 * DFUNC] = u23.x; o[3 * DFUNC] = u23.y;
    o[4 * DFUNC] = u45.x; o[5 * DFUNC] = u45.y;
    o[6 * DFUNC] = u67.x; o[7 * DFUNC] = u67.y;
}

// ---------------- A0 reduce (deterministic) --------------------------------
__global__ __launch_bounds__(256) void k_A0red() {
    int b = blockIdx.x, j = threadIdx.x;
    float v = g_A0base[b * DFUNC + j];
#pragma unroll
    for (int ks = 0; ks < KSPLIT; ks++)
        v += g_A0p[((size_t)ks * Bq + b) * DFUNC + j];
    g_A0[b * DFUNC + j] = v;
}

// ---------------- MT = (W_fc1 @ W_embed)^T ; v = W_fc1 @ b_embed ------------
__global__ __launch_bounds__(256) void k_Mv(const float* __restrict__ W1,
                                            const float* __restrict__ We,
                                            const float* __restrict__ be) {
    __shared__ float wr[DIN];
    __shared__ float part[256];
    int j = blockIdx.x, tid = threadIdx.x;
    for (int i = tid; i < DIN; i += 256) wr[i] = W1[(size_t)j * DIN + i];
    __syncthreads();
    int d = tid & 31, p = tid >> 5;
    float a = 0.f;
    int k0 = p * 128;
#pragma unroll 4
    for (int k = k0; k < k0 + 128; k++) a += wr[k] * We[k * DKEY + d];
    part[tid] = a;
    __syncthreads();
    if (tid < 32) {
        float s = part[tid];
#pragma unroll
        for (int pp = 1; pp < 8; pp++) s += part[pp * 32 + tid];
        g_MT[tid * DFUNC + j] = s;
        float vp = 0.f;
        for (int k = tid; k < DIN; k += 32) vp += wr[k] * be[k];
#pragma unroll
        for (int o = 16; o; o >>= 1) vp += __shfl_xor_sync(0xffffffffu, vp, o);
        if (tid == 0) g_v[j] = vp;
    }
}

// ---------------- prep: end-row + mask0/fs + Kacc prefix sums ---------------
__global__ __launch_bounds__(256) void k_prep(const float* __restrict__ avail,
                                              const int* __restrict__ sel,
                                              const float* __restrict__ endemb) {
    __shared__ int ss[Ss];
    int b = blockIdx.x, tid = threadIdx.x;
    if (tid < Ss) ss[tid] = sel[b * Ss + tid];
    if (tid < DKEY) g_padkey[((size_t)b * NP1 + Nn) * DKEY + tid] = endemb[tid];
    __syncthreads();
    for (int n = tid; n < NP1; n += 256) {
        int fs = 0x7FFFFFFF;
#pragma unroll
        for (int s = 0; s < Ss; s++)
            if (ss[s] == n && s < fs) fs = s;
        float m = (n == Nn) ? 1.f : avail[b * Nn + n];
        if (fs < Ss) m = 1.f;
        g_mask0[b * NP1 + n] = m;
        g_fs[b * NP1 + n] = fs;
    }
    if (tid < 32) {
        int d = tid;
        float acc = 0.f;
        const float inv_n = 1.f / 512.f;
        for (int t = 0; t < Tt; t++) {
            g_Kacc[((size_t)b * Tt + t) * DKEY + d] = acc;
            if (t < Ss) acc += g_padkey[((size_t)b * NP1 + ss[t]) * DKEY + d] * inv_n;
        }
    }
}

// ---- xg: one block per batch row, all 33 steps, weights resident ----------
__global__ __launch_bounds__(256) void k_xg(const float* __restrict__ b2,
                                            const float* __restrict__ bih,
                                            const float* __restrict__ bhh) {
    __shared__ __align__(16) float W2s[DFUNC * DKEY];
    __shared__ __align__(16) float kas[Tt * DKEY];
    __shared__ __align__(16) float xrT[DFUNC * TBT];
    __shared__ __align__(16) float xsT[DKEY * TBT];
    __shared__ __align__(16) float p2[8][DKEY * TBT];
    int b = blockIdx.x, j = threadIdx.x;
    for (int idx = j; idx < DFUNC * DKEY; idx += 256) W2s[idx] = g_W2T[idx];
    for (int idx = j; idx < Tt * DKEY; idx += 256) kas[idx] = g_Kacc[(size_t)b * Tt * DKEY + idx];
    float a0j = g_A0[b * DFUNC + j], vj = g_v[j];
    ull m2[16];
#pragma unroll
    for (int d = 0; d < 16; d++)
        m2[d] = pack2(g_MT[(2 * d) * DFUNC + j], g_MT[(2 * d + 1) * DFUNC + j]);
    float base_ih = (j < G4) ? (bih[j] + bhh[j]) : 0.f;
    __syncthreads();
    for (int t0 = 0; t0 < Tt; t0 += TBT) {
        float rr[TBT];
#pragma unroll
        for (int tt = 0; tt < TBT; tt++) {
            int t = t0 + tt;
            float r = 0.f;
            if (t < Tt) {
                ull acc = 0ull;
                const ull* ka2 = (const ull*)&kas[t * DKEY];
#pragma unroll
                for (int d = 0; d < 16; d++) FMA2(acc, m2[d], ka2[d]);
                float2 u = unpack2(acc);
                r = fmaxf(a0j + (float)t * vj + u.x + u.y, 0.f);
            }
            rr[tt] = r;
        }
        {
            ull* xw = (ull*)&xrT[j * TBT];
            xw[0] = pack2(rr[0], rr[1]);
            xw[1] = pack2(rr[2], rr[3]);
        }
        __syncthreads();
        {
            int c = j & 31, p = j >> 5, k0 = p * 32;
            ull s01 = 0ull, s23 = 0ull;
#pragma unroll
            for (int k = k0; k < k0 + 32; k++) {
                float w = W2s[k * DKEY + c];
                ull wp = pack2(w, w);
                const ull* xp = (const ull*)&xrT[k * TBT];
                FMA2(s01, wp, xp[0]); FMA2(s23, wp, xp[1]);
            }
            ull* pp = (ull*)&p2[p][c * TBT];
            pp[0] = s01; pp[1] = s23;
        }
        __syncthreads();
        if (j < DKEY * TBT) {
            int c = j >> 2, tt = j & 3;
            float acc = b2[c];
#pragma unroll
            for (int p = 0; p < 8; p++) acc += p2[p][c * TBT + tt];
            xsT[c * TBT + tt] = acc;
        }
        __syncthreads();
        if (j < G4) {
            ull g01 = pack2(base_ih, base_ih), g23 = g01;
#pragma unroll
            for (int c = 0; c < HH; c++) {
                float w = g_WihT[c * G4 + j];
                ull wp = pack2(w, w);
                const ull* xp = (const ull*)&xsT[c * TBT];
                FMA2(g01, wp, xp[0]); FMA2(g23, wp, xp[1]);
            }
            float2 u01 = unpack2(g01), u23 = unpack2(g23);
            float gv[TBT] = {u01.x, u01.y, u23.x, u23.y};
#pragma unroll
            for (int tt = 0; tt < TBT; tt++) {
                int t = t0 + tt;
                if (t < Tt) g_G[((size_t)b * Tt + t) * G4 + j] = gv[tt];
            }
        }
        __syncthreads();
    }
}

// ---------------- LSTM scan -------------------------------------------------
__global__ __launch_bounds__(128) void k_lstm(const float* __restrict__ Whh) {
    __shared__ float wh[HH * G4];
    __shared__ float gates[G4];
    __shared__ float hs[HH], cs[HH];
    int b = blockIdx.x, g = threadIdx.x;
    for (int idx = g; idx < G4 * HH; idx += 128) {
        int gg = idx >> 5, cc = idx & 31;
        wh[cc * G4 + gg] = Whh[idx];
    }
    if (g < HH) { hs[g] = 0.f; cs[g] = 0.f; }
    __syncthreads();
    for (int t = 0; t < Tt; t++) {
        float a = g_G[((size_t)b * Tt + t) * G4 + g];
#pragma unroll
        for (int c = 0; c < HH; c++) a += hs[c] * wh[c * G4 + g];
        gates[g] = a;
        __syncthreads();
        if (g < HH) {
            float ig = gates[g], fg = gates[32 + g], gg = gates[64 + g], og = gates[96 + g];
            float si = 1.f / (1.f + expf(-ig));
            float sf = 1.f / (1.f + expf(-fg));
            float so = 1.f / (1.f + expf(-og));
            float cn = sf * cs[g] + si * tanhf(gg);
            cs[g] = cn;
            float hn = so * tanhf(cn);
            hs[g] = hn;
            g_H[((size_t)b * Tt + t) * HH + g] = hn;
        }
        __syncthreads();
    }
}

// ---------------- logits (f32x2) -------------------------------------------
__global__ __launch_bounds__(128) void k_logits(float* __restrict__ out) {
    __shared__ __align__(16) float hsm[Tt * HH];
    int b = blockIdx.y;
    int n = blockIdx.x * 128 + threadIdx.x;
    for (int i = threadIdx.x; i < Tt * HH; i += 128) hsm[i] = g_H[(size_t)b * Tt * HH + i];
    __syncthreads();
    if (n >= NP1) return;
    ull key2[16];
    const ull* kp = (const ull*)(g_padkey + ((size_t)b * NP1 + n) * DKEY);
#pragma unroll
    for (int q = 0; q < 16; q++) key2[q] = kp[q];
    int fs = g_fs[b * NP1 + n];
    float m0 = g_mask0[b * NP1 + n];
    float* ob = out + (size_t)b * Tt * NP1 + n;
    const ull* h2 = (const ull*)hsm;
    for (int t = 0; t < Tt; t++) {
        ull a0 = 0ull, a1 = 0ull, a2 = 0ull, a3 = 0ull;
#pragma unroll
        for (int q = 0; q < 16; q += 4) {
            FMA2(a0, h2[t * 16 + q + 0], key2[q + 0]);
            FMA2(a1, h2[t * 16 + q + 1], key2[q + 1]);
            FMA2(a2, h2[t * 16 + q + 2], key2[q + 2]);
            FMA2(a3, h2[t * 16 + q + 3], key2[q + 3]);
        }
        float2 u0 = unpack2(a0), u1 = unpack2(a1), u2 = unpack2(a2), u3 = unpack2(a3);
        float dot = ((u0.x + u0.y) + (u1.x + u1.y)) + ((u2.x + u2.y) + (u3.x + u3.y));
        float pen = (m0 != 0.f && t <= fs) ? 0.f : 1e9f;
        ob[(size_t)t * NP1] = dot - pen;
    }
}

// ---------------- final emb, 4 rows / block ---------------------------------
__global__ __launch_bounds__(256) void k_embout(const float* __restrict__ emb,
                                                const float* __restrict__ be,
                                                float* __restrict__ out) {
    __shared__ float ka[4][DKEY];
    int b0 = blockIdx.x * 4, tid = threadIdx.x;
    if (tid < 4 * DKEY) {
        int r = tid >> 5, d = tid & 31;
        ka[r][d] = g_Kacc[((size_t)(b0 + r) * Tt + Ss) * DKEY + d];
    }
    __syncthreads();
    for (int k = tid; k < DIN; k += 256) {
        float base = 32.f * be[k];
        float a0 = emb[(size_t)(b0 + 0) * DIN + k] + base;
        float a1 = emb[(size_t)(b0 + 1) * DIN + k] + base;
        float a2 = emb[(size_t)(b0 + 2) * DIN + k] + base;
        float a3 = emb[(size_t)(b0 + 3) * DIN + k] + base;
#pragma unroll
        for (int d = 0; d < DKEY; d++) {
            float w = g_WeT[d * DIN + k];
            a0 += ka[0][d] * w; a1 += ka[1][d] * w;
            a2 += ka[2][d] * w; a3 += ka[3][d] * w;
        }
        size_t ob = (size_t)(Bq * Tt * NP1);
        out[ob + (size_t)(b0 + 0) * DIN + k] = a0;
        out[ob + (size_t)(b0 + 1) * DIN + k] = a1;
        out[ob + (size_t)(b0 + 2) * DIN + k] = a2;
        out[ob + (size_t)(b0 + 3) * DIN + k] = a3;
    }
}

extern "C" void kernel_launch(void* const* d_in, const int* in_sizes, int n_in,
                              void* d_out, int out_size) {
    (void)in_sizes; (void)n_in;
    const float* emb    = (const float*)d_in[0];
    const float* tmask  = (const float*)d_in[1];
    const float* avail  = (const float*)d_in[2];
    const float* ent    = (const float*)d_in[3];
    const int*   sel    = (const int*)d_in[4];
    const float* endemb = (const float*)d_in[5];
    const float* Wk  = (const float*)d_in[6];
    const float* bk  = (const float*)d_in[7];
    const float* Wf  = (const float*)d_in[8];
    const float* bf  = (const float*)d_in[9];
    const float* W1  = (const float*)d_in[10];
    const float* b1  = (const float*)d_in[11];
    const float* W2  = (const float*)d_in[12];
    const float* b2  = (const float*)d_in[13];
    const float* We  = (const float*)d_in[14];
    const float* be  = (const float*)d_in[15];
    const float* Wih = (const float*)d_in[16];
    const float* bih = (const float*)d_in[17];
    const float* Whh = (const float*)d_in[18];
    const float* bhh = (const float*)d_in[19];
    float* out = (float*)d_out;

    k_transpose_all<<<372, 256>>>(W1, Wf, W2, Wih, We);
    k_padkey<<<(Bq * Nn) / 128, 256>>>(ent, Wk, bk);
    k_funcembed<<<Bq / 4, 256>>>(tmask, bf, b1);
    k_A0p<<<dim3(KSPLIT, Bq / 8), 256>>>(emb);
    k_A0red<<<Bq, 256>>>();
    k_Mv<<<DFUNC, 256>>>(W1, We, be);
    k_prep<<<Bq, 256>>>(avail, sel, endemb);
    k_xg<<<Bq, 256>>>(b2, bih, bhh);
    k_lstm<<<Bq, 128>>>(Whh);
    k_logits<<<dim3((NP1 + 127) / 128, Bq), 128>>>(out);
    if (out_size >= Bq * Tt * NP1 + Bq * DIN)
        k_embout<<<Bq / 4, 256>>>(emb, be, out);
}

// round 17
// speedup vs baseline: 3.8133x; 1.0133x over previous
#include <cuda_runtime.h>
#include <math.h>

#define Bq 256
#define Nn 512
#define NP1 513
#define Ss 32
#define Tt 33
#define DENT 256
#define DKEY 32
#define DIN 1024
#define DFUNC 256
#define DTYPE 259
#define HH 32
#define G4 128
#define TBT 4
#define KSPLIT 8

typedef unsigned long long ull;

__device__ __forceinline__ ull pack2(float x, float y) {
    ull r; asm("mov.b64 %0, {%1, %2};" : "=l"(r) : "f"(x), "f"(y)); return r;
}
__device__ __forceinline__ float2 unpack2(ull v) {
    float2 r; asm("mov.b64 {%0, %1}, %2;" : "=f"(r.x), "=f"(r.y) : "l"(v)); return r;
}
#define FMA2(acc, a, b) asm("fma.rn.f32x2 %0, %1, %2, %0;" : "+l"(acc) : "l"(a), "l"(b))

// ---------------- scratch ---------------------------------------------------
__device__ float g_padkey[Bq * NP1 * DKEY];   // [b][n][k]
__device__ float g_A0base[Bq * DFUNC];        // relu(func)+b1
__device__ float g_A0p[KSPLIT * Bq * DFUNC];  // split-K partials
__device__ float g_A0[Bq * DFUNC];
__device__ float g_MT[DKEY * DFUNC];
__device__ float g_v[DFUNC];
__device__ float g_mask0[Bq * NP1];
__device__ int   g_fs[Bq * NP1];
__device__ float g_Kacc[Bq * Tt * DKEY];
__device__ float g_G[Bq * Tt * G4];
__device__ float g_H[Bq * Tt * HH];
__device__ float g_W1T[DIN * DFUNC];
__device__ float g_WfT[DTYPE * DFUNC];
__device__ float g_W2T[DFUNC * DKEY];
__device__ float g_WihT[HH * G4];
__device__ float g_WeT[DKEY * DIN];

// ---------------- one fused transpose kernel (5 matrices) -------------------
__global__ __launch_bounds__(256) void k_transpose_all(const float* __restrict__ W1,
                                                       const float* __restrict__ Wf,
                                                       const float* __restrict__ W2,
                                                       const float* __restrict__ Wih,
                                                       const float* __restrict__ We) {
    __shared__ float tile[32][33];
    int bid = blockIdx.x;
    const float* in; float* out; int R, C, bx, by;
    if (bid < 256)      { in = W1;  out = g_W1T;  R = DFUNC; C = DIN;   bx = bid & 31; by = bid >> 5; }
    else if (bid < 328) { int t = bid - 256; in = Wf;  out = g_WfT;  R = DFUNC; C = DTYPE; bx = t % 9; by = t / 9; }
    else if (bid < 336) { int t = bid - 328; in = W2;  out = g_W2T;  R = DKEY;  C = DFUNC; bx = t; by = 0; }
    else if (bid < 340) { int t = bid - 336; in = Wih; out = g_WihT; R = G4;    C = HH;    bx = 0; by = t; }
    else                { int t = bid - 340; in = We;  out = g_WeT;  R = DIN;   C = DKEY;  bx = 0; by = t; }
    int c0 = bx * 32, r0 = by * 32;
    int x = threadIdx.x & 31, y = threadIdx.x >> 5;
#pragma unroll
    for (int i = 0; i < 32; i += 8) {
        int r = r0 + y + i, c = c0 + x;
        if (r < R && c < C) tile[y + i][x] = in[(size_t)r * C + c];
    }
    __syncthreads();
#pragma unroll
    for (int i = 0; i < 32; i += 8) {
        int r = r0 + x, c = c0 + y + i;
        if (r < R && c < C) out[(size_t)c * R + r] = tile[x][y + i];
    }
}

// ------- pad_key v2: one block per batch row, 8x8 register blocking ---------
__global__ __launch_bounds__(256, 2) void k_padkey(const float* __restrict__ ent,
                                                   const float* __restrict__ Wk,
                                                   const float* __restrict__ bk) {
    __shared__ __align__(16) float es[512][17];   // [n][kk], 68B row stride (8B-mult)
    __shared__ __align__(16) float wt[16][34];    // [kk][c], 136B stride (8B-mult)
    const int b = blockIdx.x, tid = threadIdx.x;
    const int e = tid & 63, c = (tid >> 6) << 3;
    ull acc[8][4];
#pragma unroll
    for (int r = 0; r < 8; r++)
#pragma unroll
        for (int q = 0; q < 4; q++) acc[r][q] = 0ull;
    const float4* entb = (const float4*)(ent + (size_t)b * Nn * DENT);
    for (int k0 = 0; k0 < DENT; k0 += 16) {
        __syncthreads();
        for (int idx = tid; idx < 512; idx += 256) {
            int cc = idx >> 4, kk = idx & 15;
            wt[kk][cc] = Wk[cc * DENT + k0 + kk];
        }
#pragma unroll
        for (int i = 0; i < 8; i++) {
            int f4i = tid + i * 256;
            int n = f4i >> 2, k4 = f4i & 3;
            float4 v = entb[(size_t)n * 64 + (k0 >> 2) + k4];
            es[n][k4 * 4 + 0] = v.x; es[n][k4 * 4 + 1] = v.y;
            es[n][k4 * 4 + 2] = v.z; es[n][k4 * 4 + 3] = v.w;
        }
        __syncthreads();
#pragma unroll
        for (int kk = 0; kk < 16; kk++) {
            const ull* w2 = (const ull*)&wt[kk][c];   // broadcast within warp
            ull w01 = w2[0], w23 = w2[1], w45 = w2[2], w67 = w2[3];
#pragma unroll
            for (int r = 0; r < 8; r++) {
                float av = es[e + 64 * r][kk];        // conflict-free (stride 17)
                ull pa = pack2(av, av);
                FMA2(acc[r][0], pa, w01); FMA2(acc[r][1], pa, w23);
                FMA2(acc[r][2], pa, w45); FMA2(acc[r][3], pa, w67);
            }
        }
    }
#pragma unroll
    for (int r = 0; r < 8; r++) {
        int n = e + 64 * r;
        float* o = g_padkey + ((size_t)b * NP1 + n) * DKEY + c;
#pragma unroll
        for (int q = 0; q < 4; q++) {
            float2 u = unpack2(acc[r][q]);
            o[2 * q]     = u.x + bk[c + 2 * q];
            o[2 * q + 1] = u.y + bk[c + 2 * q + 1];
        }
    }
}

// ------- prep2: mask/fs + end-row + selected-key GEMM + Kacc prefix ---------
__global__ __launch_bounds__(256) void k_prep2(const float* __restrict__ avail,
                                               const int* __restrict__ sel,
                                               const float* __restrict__ ent,
                                               const float* __restrict__ Wk,
                                               const float* __restrict__ bk,
                                               const float* __restrict__ endemb) {
    __shared__ int ss[Ss];
    __shared__ float es2[Ss][DENT + 1];   // 32 x 257
    __shared__ float wkc[DKEY][65];       // 32 x 65 (64-k chunk)
    __shared__ float ksm[Ss][DKEY + 1];
    int b = blockIdx.x, tid = threadIdx.x;
    if (tid < Ss) ss[tid] = sel[b * Ss + tid];
    if (tid >= 64 && tid < 64 + DKEY)
        g_padkey[((size_t)b * NP1 + Nn) * DKEY + (tid - 64)] = endemb[tid - 64];
    __syncthreads();
    for (int n = tid; n < NP1; n += 256) {
        int fs = 0x7FFFFFFF;
#pragma unroll
        for (int s = 0; s < Ss; s++)
            if (ss[s] == n && s < fs) fs = s;
        float m = (n == Nn) ? 1.f : avail[b * Nn + n];
        if (fs < Ss) m = 1.f;
        g_mask0[b * NP1 + n] = m;
        g_fs[b * NP1 + n] = fs;
    }
    for (int idx = tid; idx < Ss * DENT; idx += 256) {
        int s = idx >> 8, k = idx & 255;
        es2[s][k] = ent[((size_t)b * Nn + ss[s]) * DENT + k];
    }
    int s = tid >> 3, dg = (tid & 7) * 4;
    float a0 = 0.f, a1 = 0.f, a2 = 0.f, a3 = 0.f;
    for (int k0 = 0; k0 < DENT; k0 += 64) {
        __syncthreads();   // es2 ready (first iter) / wkc reuse safe
        for (int idx = tid; idx < DKEY * 64; idx += 256) {
            int d = idx >> 6, kk = idx & 63;
            wkc[d][kk] = Wk[d * DENT + k0 + kk];
        }
        __syncthreads();
#pragma unroll 8
        for (int kk = 0; kk < 64; kk++) {
            float av = es2[s][k0 + kk];
            a0 += av * wkc[dg + 0][kk]; a1 += av * wkc[dg + 1][kk];
            a2 += av * wkc[dg + 2][kk]; a3 += av * wkc[dg + 3][kk];
        }
    }
    ksm[s][dg + 0] = a0 + bk[dg + 0]; ksm[s][dg + 1] = a1 + bk[dg + 1];
    ksm[s][dg + 2] = a2 + bk[dg + 2]; ksm[s][dg + 3] = a3 + bk[dg + 3];
    __syncthreads();
    if (tid < DKEY) {
        float acc = 0.f;
        const float inv_n = 1.f / 512.f;
        for (int t = 0; t < Tt; t++) {
            g_Kacc[((size_t)b * Tt + t) * DKEY + tid] = acc;
            if (t < Ss) acc += ksm[t][tid] * inv_n;
        }
    }
}

// ---------------- A0base = relu(tmask@WfT + bf) + b1 ------------------------
__global__ __launch_bounds__(256) void k_funcembed(const float* __restrict__ tmask,
                                                   const float* __restrict__ bf,
                                                   const float* __restrict__ b1) {
    __shared__ float ts[4][DTYPE + 1];
    int b0 = blockIdx.x * 4, j = threadIdx.x;
#pragma unroll
    for (int bb = 0; bb < 4; bb++)
        for (int i = j; i < DTYPE; i += 256) ts[bb][i] = tmask[(size_t)(b0 + bb) * DTYPE + i];
    __syncthreads();
    float a0 = 0.f, a1 = 0.f, a2 = 0.f, a3 = 0.f;
    int k = 0;
    for (; k + 8 <= DTYPE; k += 8) {
        float w[8];
#pragma unroll
        for (int u = 0; u < 8; u++) w[u] = g_WfT[(k + u) * DFUNC + j];
#pragma unroll
        for (int u = 0; u < 8; u++) {
            a0 += ts[0][k + u] * w[u]; a1 += ts[1][k + u] * w[u];
            a2 += ts[2][k + u] * w[u]; a3 += ts[3][k + u] * w[u];
        }
    }
    for (; k < DTYPE; k++) {
        float w = g_WfT[k * DFUNC + j];
        a0 += ts[0][k] * w; a1 += ts[1][k] * w;
        a2 += ts[2][k] * w; a3 += ts[3][k] * w;
    }
    float bias = bf[j], add = b1[j];
    g_A0base[(b0 + 0) * DFUNC + j] = fmaxf(a0 + bias, 0.f) + add;
    g_A0base[(b0 + 1) * DFUNC + j] = fmaxf(a1 + bias, 0.f) + add;
    g_A0base[(b0 + 2) * DFUNC + j] = fmaxf(a2 + bias, 0.f) + add;
    g_A0base[(b0 + 3) * DFUNC + j] = fmaxf(a3 + bias, 0.f) + add;
}

// ---------------- A0 partials: split-K GEMM ---------------------------------
__global__ __launch_bounds__(256) void k_A0p(const float* __restrict__ emb) {
    __shared__ __align__(16) float esi[128 * 8];
    int ks = blockIdx.x, bg = blockIdx.y;
    int b0 = bg * 8, k0 = ks * 128;
    int j = threadIdx.x;
    for (int idx = j; idx < 1024; idx += 256) {
        int r = idx >> 7, k = idx & 127;
        esi[k * 8 + r] = emb[(size_t)(b0 + r) * DIN + k0 + k];
    }
    __syncthreads();
    ull a01 = 0ull, a23 = 0ull, a45 = 0ull, a67 = 0ull;
    for (int k = 0; k < 128; k += 8) {
        float w[8];
#pragma unroll
        for (int u = 0; u < 8; u++) w[u] = g_W1T[(size_t)(k0 + k + u) * DFUNC + j];
#pragma unroll
        for (int u = 0; u < 8; u++) {
            ull wp = pack2(w[u], w[u]);
            const ull* ep = (const ull*)&esi[(k + u) * 8];
            FMA2(a01, wp, ep[0]); FMA2(a23, wp, ep[1]);
            FMA2(a45, wp, ep[2]); FMA2(a67, wp, ep[3]);
        }
    }
    float2 u01 = unpack2(a01), u23 = unpack2(a23), u45 = unpack2(a45), u67 = unpack2(a67);
    float* o = g_A0p + ((size_t)ks * Bq + b0) * DFUNC + j;
    o[0 * DFUNC] = u01.x; o[1 * DFUNC] = u01.y;
    o[2 * DFUNC] = u23.x; o[3 * DFUNC] = u23.y;
    o[4 * DFUNC] = u45.x; o[5 * DFUNC] = u45.y;
    o[6 * DFUNC] = u67.x; o[7 * DFUNC] = u67.y;
}

__global__ __launch_bounds__(256) void k_A0red() {
    int b = blockIdx.x, j = threadIdx.x;
    float v = g_A0base[b * DFUNC + j];
#pragma unroll
    for (int ks = 0; ks < KSPLIT; ks++)
        v += g_A0p[((size_t)ks * Bq + b) * DFUNC + j];
    g_A0[b * DFUNC + j] = v;
}

// ---------------- MT = (W_fc1 @ W_embed)^T ; v = W_fc1 @ b_embed ------------
__global__ __launch_bounds__(256) void k_Mv(const float* __restrict__ W1,
                                            const float* __restrict__ We,
                                            const float* __restrict__ be) {
    __shared__ float wr[DIN];
    __shared__ float part[256];
    int j = blockIdx.x, tid = threadIdx.x;
    for (int i = tid; i < DIN; i += 256) wr[i] = W1[(size_t)j * DIN + i];
    __syncthreads();
    int d = tid & 31, p = tid >> 5;
    float a = 0.f;
    int k0 = p * 128;
#pragma unroll 4
    for (int k = k0; k < k0 + 128; k++) a += wr[k] * We[k * DKEY + d];
    part[tid] = a;
    __syncthreads();
    if (tid < 32) {
        float s = part[tid];
#pragma unroll
        for (int pp = 1; pp < 8; pp++) s += part[pp * 32 + tid];
        g_MT[tid * DFUNC + j] = s;
        float vp = 0.f;
        for (int k = tid; k < DIN; k += 32) vp += wr[k] * be[k];
#pragma unroll
        for (int o = 16; o; o >>= 1) vp += __shfl_xor_sync(0xffffffffu, vp, o);
        if (tid == 0) g_v[j] = vp;
    }
}

// ---- xg: one block per batch row, all 33 steps, weights resident ----------
__global__ __launch_bounds__(256) void k_xg(const float* __restrict__ b2,
                                            const float* __restrict__ bih,
                                            const float* __restrict__ bhh) {
    __shared__ __align__(16) float W2s[DFUNC * DKEY];
    __shared__ __align__(16) float kas[Tt * DKEY];
    __shared__ __align__(16) float xrT[DFUNC * TBT];
    __shared__ __align__(16) float xsT[DKEY * TBT];
    __shared__ __align__(16) float p2[8][DKEY * TBT];
    int b = blockIdx.x, j = threadIdx.x;
    for (int idx = j; idx < DFUNC * DKEY; idx += 256) W2s[idx] = g_W2T[idx];
    for (int idx = j; idx < Tt * DKEY; idx += 256) kas[idx] = g_Kacc[(size_t)b * Tt * DKEY + idx];
    float a0j = g_A0[b * DFUNC + j], vj = g_v[j];
    ull m2[16];
#pragma unroll
    for (int d = 0; d < 16; d++)
        m2[d] = pack2(g_MT[(2 * d) * DFUNC + j], g_MT[(2 * d + 1) * DFUNC + j]);
    float base_ih = (j < G4) ? (bih[j] + bhh[j]) : 0.f;
    __syncthreads();
    for (int t0 = 0; t0 < Tt; t0 += TBT) {
        float rr[TBT];
#pragma unroll
        for (int tt = 0; tt < TBT; tt++) {
            int t = t0 + tt;
            float r = 0.f;
            if (t < Tt) {
                ull acc = 0ull;
                const ull* ka2 = (const ull*)&kas[t * DKEY];
#pragma unroll
                for (int d = 0; d < 16; d++) FMA2(acc, m2[d], ka2[d]);
                float2 u = unpack2(acc);
                r = fmaxf(a0j + (float)t * vj + u.x + u.y, 0.f);
            }
            rr[tt] = r;
        }
        {
            ull* xw = (ull*)&xrT[j * TBT];
            xw[0] = pack2(rr[0], rr[1]);
            xw[1] = pack2(rr[2], rr[3]);
        }
        __syncthreads();
        {
            int c = j & 31, p = j >> 5, k0 = p * 32;
            ull s01 = 0ull, s23 = 0ull;
#pragma unroll
            for (int k = k0; k < k0 + 32; k++) {
                float w = W2s[k * DKEY + c];
                ull wp = pack2(w, w);
                const ull* xp = (const ull*)&xrT[k * TBT];
                FMA2(s01, wp, xp[0]); FMA2(s23, wp, xp[1]);
            }
            ull* pp = (ull*)&p2[p][c * TBT];
            pp[0] = s01; pp[1] = s23;
        }
        __syncthreads();
        if (j < DKEY * TBT) {
            int c = j >> 2, tt = j & 3;
            float acc = b2[c];
#pragma unroll
            for (int p = 0; p < 8; p++) acc += p2[p][c * TBT + tt];
            xsT[c * TBT + tt] = acc;
        }
        __syncthreads();
        if (j < G4) {
            ull g01 = pack2(base_ih, base_ih), g23 = g01;
#pragma unroll
            for (int c = 0; c < HH; c++) {
                float w = g_WihT[c * G4 + j];
                ull wp = pack2(w, w);
                const ull* xp = (const ull*)&xsT[c * TBT];
                FMA2(g01, wp, xp[0]); FMA2(g23, wp, xp[1]);
            }
            float2 u01 = unpack2(g01), u23 = unpack2(g23);
            float gv[TBT] = {u01.x, u01.y, u23.x, u23.y};
#pragma unroll
            for (int tt = 0; tt < TBT; tt++) {
                int t = t0 + tt;
                if (t < Tt) g_G[((size_t)b * Tt + t) * G4 + j] = gv[tt];
            }
        }
        __syncthreads();
    }
}

// ---------------- LSTM scan -------------------------------------------------
__global__ __launch_bounds__(128) void k_lstm(const float* __restrict__ Whh) {
    __shared__ float wh[HH * G4];
    __shared__ float gates[G4];
    __shared__ float hs[HH], cs[HH];
    int b = blockIdx.x, g = threadIdx.x;
    for (int idx = g; idx < G4 * HH; idx += 128) {
        int gg = idx >> 5, cc = idx & 31;
        wh[cc * G4 + gg] = Whh[idx];
    }
    if (g < HH) { hs[g] = 0.f; cs[g] = 0.f; }
    __syncthreads();
    for (int t = 0; t < Tt; t++) {
        float a = g_G[((size_t)b * Tt + t) * G4 + g];
#pragma unroll
        for (int c = 0; c < HH; c++) a += hs[c] * wh[c * G4 + g];
        gates[g] = a;
        __syncthreads();
        if (g < HH) {
            float ig = gates[g], fg = gates[32 + g], gg = gates[64 + g], og = gates[96 + g];
            float si = 1.f / (1.f + expf(-ig));
            float sf = 1.f / (1.f + expf(-fg));
            float so = 1.f / (1.f + expf(-og));
            float cn = sf * cs[g] + si * tanhf(gg);
            cs[g] = cn;
            float hn = so * tanhf(cn);
            hs[g] = hn;
            g_H[((size_t)b * Tt + t) * HH + g] = hn;
        }
        __syncthreads();
    }
}

// ---------------- logits (f32x2) -------------------------------------------
__global__ __launch_bounds__(128) void k_logits(float* __restrict__ out) {
    __shared__ __align__(16) float hsm[Tt * HH];
    int b = blockIdx.y;
    int n = blockIdx.x * 128 + threadIdx.x;
    for (int i = threadIdx.x; i < Tt * HH; i += 128) hsm[i] = g_H[(size_t)b * Tt * HH + i];
    __syncthreads();
    if (n >= NP1) return;
    ull key2[16];
    const ull* kp = (const ull*)(g_padkey + ((size_t)b * NP1 + n) * DKEY);
#pragma unroll
    for (int q = 0; q < 16; q++) key2[q] = kp[q];
    int fs = g_fs[b * NP1 + n];
    float m0 = g_mask0[b * NP1 + n];
    float* ob = out + (size_t)b * Tt * NP1 + n;
    const ull* h2 = (const ull*)hsm;
    for (int t = 0; t < Tt; t++) {
        ull a0 = 0ull, a1 = 0ull, a2 = 0ull, a3 = 0ull;
#pragma unroll
        for (int q = 0; q < 16; q += 4) {
            FMA2(a0, h2[t * 16 + q + 0], key2[q + 0]);
            FMA2(a1, h2[t * 16 + q + 1], key2[q + 1]);
            FMA2(a2, h2[t * 16 + q + 2], key2[q + 2]);
            FMA2(a3, h2[t * 16 + q + 3], key2[q + 3]);
        }
        float2 u0 = unpack2(a0), u1 = unpack2(a1), u2 = unpack2(a2), u3 = unpack2(a3);
        float dot = ((u0.x + u0.y) + (u1.x + u1.y)) + ((u2.x + u2.y) + (u3.x + u3.y));
        float pen = (m0 != 0.f && t <= fs) ? 0.f : 1e9f;
        ob[(size_t)t * NP1] = dot - pen;
    }
}

// ---------------- final emb, 4 rows / block ---------------------------------
__global__ __launch_bounds__(256) void k_embout(const float* __restrict__ emb,
                                                const float* __restrict__ be,
                                                float* __restrict__ out) {
    __shared__ float ka[4][DKEY];
    int b0 = blockIdx.x * 4, tid = threadIdx.x;
    if (tid < 4 * DKEY) {
        int r = tid >> 5, d = tid & 31;
        ka[r][d] = g_Kacc[((size_t)(b0 + r) * Tt + Ss) * DKEY + d];
    }
    __syncthreads();
    for (int k = tid; k < DIN; k += 256) {
        float base = 32.f * be[k];
        float a0 = emb[(size_t)(b0 + 0) * DIN + k] + base;
        float a1 = emb[(size_t)(b0 + 1) * DIN + k] + base;
        float a2 = emb[(size_t)(b0 + 2) * DIN + k] + base;
        float a3 = emb[(size_t)(b0 + 3) * DIN + k] + base;
#pragma unroll
        for (int d = 0; d < DKEY; d++) {
            float w = g_WeT[d * DIN + k];
            a0 += ka[0][d] * w; a1 += ka[1][d] * w;
            a2 += ka[2][d] * w; a3 += ka[3][d] * w;
        }
        size_t ob = (size_t)(Bq * Tt * NP1);
        out[ob + (size_t)(b0 + 0) * DIN + k] = a0;
        out[ob + (size_t)(b0 + 1) * DIN + k] = a1;
        out[ob + (size_t)(b0 + 2) * DIN + k] = a2;
        out[ob + (size_t)(b0 + 3) * DIN + k] = a3;
    }
}

// ---------------- launch: fork/join multi-stream graph ----------------------
namespace {
struct Ctx {
    cudaStream_t s1, s2, s3;
    cudaEvent_t ev0, ev1, ev2, ev3, ev4, evT;
    Ctx() {
        cudaStreamCreateWithFlags(&s1, cudaStreamNonBlocking);
        cudaStreamCreateWithFlags(&s2, cudaStreamNonBlocking);
        cudaStreamCreateWithFlags(&s3, cudaStreamNonBlocking);
        cudaEventCreateWithFlags(&ev0, cudaEventDisableTiming);
        cudaEventCreateWithFlags(&ev1, cudaEventDisableTiming);
        cudaEventCreateWithFlags(&ev2, cudaEventDisableTiming);
        cudaEventCreateWithFlags(&ev3, cudaEventDisableTiming);
        cudaEventCreateWithFlags(&ev4, cudaEventDisableTiming);
        cudaEventCreateWithFlags(&evT, cudaEventDisableTiming);
    }
};
}

extern "C" void kernel_launch(void* const* d_in, const int* in_sizes, int n_in,
                              void* d_out, int out_size) {
    (void)in_sizes; (void)n_in;
    static Ctx ctx;   // created on first (non-captured) correctness call
    const float* emb    = (const float*)d_in[0];
    const float* tmask  = (const float*)d_in[1];
    const float* avail  = (const float*)d_in[2];
    const float* ent    = (const float*)d_in[3];
    const int*   sel    = (const int*)d_in[4];
    const float* endemb = (const float*)d_in[5];
    const float* Wk  = (const float*)d_in[6];
    const float* bk  = (const float*)d_in[7];
    const float* Wf  = (const float*)d_in[8];
    const float* bf  = (const float*)d_in[9];
    const float* W1  = (const float*)d_in[10];
    const float* b1  = (const float*)d_in[11];
    const float* W2  = (const float*)d_in[12];
    const float* b2  = (const float*)d_in[13];
    const float* We  = (const float*)d_in[14];
    const float* be  = (const float*)d_in[15];
    const float* Wih = (const float*)d_in[16];
    const float* bih = (const float*)d_in[17];
    const float* Whh = (const float*)d_in[18];
    const float* bhh = (const float*)d_in[19];
    float* out = (float*)d_out;

    cudaEventRecord(ctx.ev0, 0);

    // s1: the big pad_key GEMM
    cudaStreamWaitEvent(ctx.s1, ctx.ev0, 0);
    k_padkey<<<Bq, 256, 0, ctx.s1>>>(ent, Wk, bk);
    cudaEventRecord(ctx.ev1, ctx.s1);

    // s2: transposes -> A0 partials ; later embout
    cudaStreamWaitEvent(ctx.s2, ctx.ev0, 0);
    k_transpose_all<<<372, 256, 0, ctx.s2>>>(W1, Wf, W2, Wih, We);
    cudaEventRecord(ctx.evT, ctx.s2);
    k_A0p<<<dim3(KSPLIT, Bq / 8), 256, 0, ctx.s2>>>(emb);
    cudaEventRecord(ctx.ev2, ctx.s2);

    // s3: prep (mask/fs/endrow/Kacc) -> funcembed (needs WfT) -> Mv
    cudaStreamWaitEvent(ctx.s3, ctx.ev0, 0);
    k_prep2<<<Bq, 256, 0, ctx.s3>>>(avail, sel, ent, Wk, bk, endemb);
    cudaStreamWaitEvent(ctx.s3, ctx.evT, 0);
    k_funcembed<<<Bq / 4, 256, 0, ctx.s3>>>(tmask, bf, b1);
    k_Mv<<<DFUNC, 256, 0, ctx.s3>>>(W1, We, be);
    cudaEventRecord(ctx.ev3, ctx.s3);

    // s2 tail: embout (needs WeT from s2 + Kacc from s3)
    cudaStreamWaitEvent(ctx.s2, ctx.ev3, 0);
    if (out_size >= Bq * Tt * NP1 + Bq * DIN)
        k_embout<<<Bq / 4, 256, 0, ctx.s2>>>(emb, be, out);
    cudaEventRecord(ctx.ev4, ctx.s2);

    // main chain on stream 0
    cudaStreamWaitEvent(0, ctx.ev2, 0);
    cudaStreamWaitEvent(0, ctx.ev3, 0);
    k_A0red<<<Bq, 256>>>();
    k_xg<<<Bq, 256>>>(b2, bih, bhh);
    k_lstm<<<Bq, 128>>>(Whh);
    cudaStreamWaitEvent(0, ctx.ev1, 0);
    k_logits<<<dim3((NP1 + 127) / 128, Bq), 128>>>(out);
    cudaStreamWaitEvent(0, ctx.ev4, 0);
}